// round 13
// baseline (speedup 1.0000x reference)
#include <cuda_runtime.h>
#include <cuda_fp16.h>
#include <math.h>
#include <stdint.h>

#define NMAX 10000
#define EMAX 160000
#define KT   125
#define CI1  64
#define CC   128
#define LD1  (KT*CI1 + CI1)    // 8064
#define LD2  (KT*CC + CC)      // 16128

// ---------------- scratch (device globals: no allocations allowed) ----------
__device__ __align__(1024) __half g_acc[(size_t)NMAX * LD2];  // 322MB
__device__ __align__(1024) __half g_wt1[CC * LD1];
__device__ __align__(1024) __half g_wt2[CC * LD2];
__device__ __align__(1024) __half g_wts[CC * CC];
__device__ __align__(1024) __half g_sin[NMAX * CC];           // [s_agg | x]
__device__ __align__(1024) __half g_h1e[NMAX * CC];           // elu(bn1(conv1)) fp16
__device__ __align__(1024) float g_part[3 * (size_t)NMAX * CC];
__device__ __align__(1024) float g_out1[NMAX * CC];
__device__ __align__(1024) float g_out2[NMAX * CC];
__device__ __align__(1024) float g_outs[NMAX * CC];
__device__ __align__(16) float g_w8  [EMAX * 8];   // CSR-ordered basis weights
__device__ __align__(16) int   g_idx8[EMAX * 8];   // CSR-ordered kernel indices
__device__ int   g_srco[EMAX];
__device__ int   g_rowptr[NMAX + 1];
__device__ int   g_cursor[NMAX];
__device__ int   g_degcnt[NMAX];
__device__ float g_red  [6 * CC];
__device__ float g_scale[3 * CC];
__device__ float g_shift[3 * CC];

// ---------------- helpers ----------------------------------------------------
__device__ __forceinline__ uint32_t smem_u32(const void* p) {
    uint32_t a;
    asm("{ .reg .u64 t; cvta.to.shared.u64 t, %1; cvt.u32.u64 %0, t; }" : "=r"(a) : "l"(p));
    return a;
}
__device__ __forceinline__ void cp_async16(uint32_t dst, const void* src, int vsize) {
    asm volatile("cp.async.cg.shared.global [%0], [%1], 16, %2;"
                 :: "r"(dst), "l"(src), "r"(vsize) : "memory");
}
#define CP_COMMIT() asm volatile("cp.async.commit_group;" ::: "memory")
#define CP_WAIT(n)  asm volatile("cp.async.wait_group %0;" :: "n"(n) : "memory")

__device__ __forceinline__ void ldsm4(uint32_t* r, uint32_t addr) {
    asm volatile("ldmatrix.sync.aligned.m8n8.x4.shared.b16 {%0,%1,%2,%3}, [%4];"
                 : "=r"(r[0]), "=r"(r[1]), "=r"(r[2]), "=r"(r[3]) : "r"(addr));
}
__device__ __forceinline__ void mma_f16(float* c, const uint32_t* a, uint32_t b0, uint32_t b1) {
    asm volatile("mma.sync.aligned.m16n8k16.row.col.f32.f16.f16.f32 "
                 "{%0,%1,%2,%3}, {%4,%5,%6,%7}, {%8,%9}, {%0,%1,%2,%3};"
                 : "+f"(c[0]), "+f"(c[1]), "+f"(c[2]), "+f"(c[3])
                 : "r"(a[0]), "r"(a[1]), "r"(a[2]), "r"(a[3]), "r"(b0), "r"(b1));
}

// ---------------- CSR build --------------------------------------------------
__global__ void k_pre(const int* __restrict__ dst, int E) {
    int e = blockIdx.x * blockDim.x + threadIdx.x;
    if (e < E) atomicAdd(&g_degcnt[dst[e]], 1);
}

__global__ void k_scan(int n) {
    __shared__ int sh[1024];
    __shared__ int carry;
    int t = threadIdx.x;
    if (t == 0) carry = 0;
    __syncthreads();
    for (int base = 0; base < n; base += 1024) {
        int i = base + t;
        int v = (i < n) ? g_degcnt[i] : 0;
        sh[t] = v;
        __syncthreads();
        for (int off = 1; off < 1024; off <<= 1) {
            int tv = (t >= off) ? sh[t - off] : 0;
            __syncthreads();
            sh[t] += tv;
            __syncthreads();
        }
        if (i < n) {
            int ex = carry + sh[t] - v;
            g_rowptr[i] = ex;
            g_cursor[i] = ex;
        }
        __syncthreads();
        if (t == 0) carry += sh[1023];
        __syncthreads();
    }
    if (t == 0) g_rowptr[n] = carry;
}

__global__ void k_fill(const float* __restrict__ attr, const int* __restrict__ src,
                       const int* __restrict__ dst, int E) {
    int e = blockIdx.x * blockDim.x + threadIdx.x;
    if (e >= E) return;
    int pos = atomicAdd(&g_cursor[dst[e]], 1);
    g_srco[pos] = src[e];
    float v0 = attr[e * 3 + 0] * 4.f, v1 = attr[e * 3 + 1] * 4.f, v2 = attr[e * 3 + 2] * 4.f;
    float b0 = floorf(v0), b1 = floorf(v1), b2 = floorf(v2);
    float f0 = v0 - b0, f1 = v1 - b1, f2 = v2 - b2;
    int i0 = (int)b0, i1 = (int)b1, i2 = (int)b2;
#pragma unroll
    for (int m = 0; m < 8; m++) {
        int t0 = m & 1, t1 = (m >> 1) & 1, t2 = (m >> 2) & 1;
        float w = (t0 ? f0 : 1.f - f0) * (t1 ? f1 : 1.f - f1) * (t2 ? f2 : 1.f - f2);
        int c0 = min(max(i0 + t0, 0), 4);
        int c1 = min(max(i1 + t1, 0), 4);
        int c2 = min(max(i2 + t2, 0), 4);
        g_idx8[pos * 8 + m] = (c0 * 5 + c1) * 5 + c2;
        g_w8[pos * 8 + m] = w;
    }
}

// ---------------- aggregation: 512 thr = (512/CIT) edge-groups x CIT ch ------
template <int CIT, int WITH_S, typename T>
__global__ __launch_bounds__(512)
void k_agg(const T* __restrict__ X, const float* __restrict__ Xroot, int ldacc) {
    extern __shared__ float acc[];      // KT*CIT floats
    __shared__ float sred[512];
    const int GR = 512 / CIT;
    int n = blockIdx.x;
    int tid = threadIdx.x;
    int c = tid & (CIT - 1), grp = tid / CIT;
    float4 z4 = make_float4(0.f, 0.f, 0.f, 0.f);
    for (int i = tid; i < KT * CIT / 4; i += 512) ((float4*)acc)[i] = z4;
    int jb = g_rowptr[n], je = g_rowptr[n + 1];
    float invd = (je > jb) ? 1.f / (float)(je - jb) : 1.f;
    float ss = 0.f;
    __syncthreads();

    const int4*   ip = (const int4*)g_idx8;
    const float4* wp = (const float4*)g_w8;
    for (int j = jb + grp; j < je; j += GR) {
        float xc = (float)X[(size_t)g_srco[j] * CIT + c];
        int4 ca = ip[j * 2], cb = ip[j * 2 + 1];
        float4 va = wp[j * 2], vb = wp[j * 2 + 1];
        if (WITH_S) ss += xc;
        atomicAdd(&acc[ca.x * CIT + c], va.x * xc);
        atomicAdd(&acc[ca.y * CIT + c], va.y * xc);
        atomicAdd(&acc[ca.z * CIT + c], va.z * xc);
        atomicAdd(&acc[ca.w * CIT + c], va.w * xc);
        atomicAdd(&acc[cb.x * CIT + c], vb.x * xc);
        atomicAdd(&acc[cb.y * CIT + c], vb.y * xc);
        atomicAdd(&acc[cb.z * CIT + c], vb.z * xc);
        atomicAdd(&acc[cb.w * CIT + c], vb.w * xc);
    }
    __syncthreads();

    // vectorized streaming writeout: float4 -> 4 halves (one 8B .cs store)
    size_t base = (size_t)n * ldacc;
    for (int i = tid; i < KT * CIT / 4; i += 512) {
        float4 v = ((const float4*)acc)[i];
        int bin = i / (CIT / 4);
        int ch  = (i % (CIT / 4)) * 4;
        __half2 h0 = __floats2half2_rn(v.x * invd, v.y * invd);
        __half2 h1 = __floats2half2_rn(v.z * invd, v.w * invd);
        float2 pk = make_float2(__uint_as_float(*(uint32_t*)&h0),
                                __uint_as_float(*(uint32_t*)&h1));
        __stcs((float2*)(g_acc + base + (size_t)bin * CIT + ch), pk);
    }
    if (tid < CIT)
        g_acc[base + (size_t)KT * CIT + tid] = (__half)(float)X[(size_t)n * CIT + tid];
    if (WITH_S) {
        sred[tid] = ss;
        __syncthreads();
        if (tid < 64) {
            float s = 0.f;
#pragma unroll
            for (int q = 0; q < GR; q++) s += sred[tid + q * 64];
            g_sin[n * CC + tid]       = __float2half(s * invd);
            g_sin[n * CC + CI1 + tid] = __float2half(Xroot[n * CI1 + tid]);
        }
    }
}

// fused tiled transpose of all three weight sets -> wt[n][k] fp16
__global__ void k_transp3(const float* __restrict__ W1, const float* __restrict__ Wr1,
                          const float* __restrict__ W2, const float* __restrict__ Wr2,
                          const float* __restrict__ Ws, const float* __restrict__ Wrs,
                          __half* __restrict__ wt1, __half* __restrict__ wt2,
                          __half* __restrict__ wts) {
    __shared__ float tile[32][33];
    const float *W, *Wr; __half* out; int Kmain, Ktot;
    if (blockIdx.z == 0) { W = W1; Wr = Wr1; out = wt1; Kmain = KT * CI1; Ktot = LD1; }
    else if (blockIdx.z == 1) { W = W2; Wr = Wr2; out = wt2; Kmain = KT * CC; Ktot = LD2; }
    else { W = Ws; Wr = Wrs; out = wts; Kmain = CI1; Ktot = CC; }
    int kb = blockIdx.x * 32, nb = blockIdx.y * 32;
    if (kb >= Ktot) return;
    int tx = threadIdx.x, ty = threadIdx.y;
#pragma unroll
    for (int i = 0; i < 32; i += 8) {
        int k = kb + ty + i;
        const float* srcp = (k < Kmain) ? &W[(size_t)k * CC] : &Wr[(size_t)(k - Kmain) * CC];
        tile[ty + i][tx] = srcp[nb + tx];
    }
    __syncthreads();
#pragma unroll
    for (int i = 0; i < 32; i += 8) {
        int nn = nb + ty + i;
        out[(size_t)nn * Ktot + kb + tx] = __float2half(tile[tx][ty + i]);
    }
}

// ---------------- fp16 mma.sync GEMM with ldmatrix feed -----------------------
#define BK 64
#define NSTAGE 3
#define STG_BYTES 32768
#define TILE_BYTES 16384

__global__ __launch_bounds__(256, 2)
void k_mgemm(const __half* __restrict__ A, const __half* __restrict__ B, int ld,
             int M, float* __restrict__ P, int pstride, int chunks) {
    extern __shared__ char sm[];
    int tid = threadIdx.x, lane = tid & 31, wid = tid >> 5;
    int m0 = blockIdx.x * 128;
    int kb0 = blockIdx.y * chunks * BK;

    int pr_r = tid >> 1;
    int pr_h = (tid & 1) * 4;
    int grow = m0 + pr_r;
    int vA = (grow < M) ? 16 : 0;
    const __half* Abase = A + (size_t)grow * ld + kb0;
    const __half* Bbase = B + (size_t)pr_r * ld + kb0;

    const int warp_m0 = (wid & 3) * 32;
    const int warp_n0 = (wid >> 2) * 64;
    int g = lane >> 2, t = lane & 3;

    uint32_t aoff[2]; int arx[2];
#pragma unroll
    for (int mf = 0; mf < 2; mf++) {
        int r = warp_m0 + mf * 16 + (lane & 15);
        aoff[mf] = r * 128; arx[mf] = r & 7;
    }
    int acb = lane >> 4;
    int grp = lane >> 3;
    int nf_half = grp >> 1, bcb = grp & 1;
    uint32_t boff[4]; int brx[4];
#pragma unroll
    for (int nfp = 0; nfp < 4; nfp++) {
        int r = warp_n0 + (nfp * 2 + nf_half) * 8 + (lane & 7);
        boff[nfp] = r * 128; brx[nfp] = r & 7;
    }

    float c[2][8][4];
#pragma unroll
    for (int i = 0; i < 2; i++)
#pragma unroll
        for (int j = 0; j < 8; j++)
#pragma unroll
            for (int q = 0; q < 4; q++) c[i][j][q] = 0.f;

    uint32_t smb = smem_u32(sm);

#define ISSUE(IT) do { \
    int _it = (IT); \
    if (_it < chunks) { \
        int _s = _it % NSTAGE; \
        uint32_t _dA = smb + _s * STG_BYTES + pr_r * 128; \
        uint32_t _dB = _dA + TILE_BYTES; \
        const __half* _sa = Abase + _it * BK; \
        const __half* _sb = Bbase + _it * BK; \
        _Pragma("unroll") \
        for (int _j = 0; _j < 4; _j++) { \
            int _c = pr_h + _j; \
            int _sc = _c ^ (pr_r & 7); \
            cp_async16(_dA + _sc * 16, _sa + _c * 8, vA); \
            cp_async16(_dB + _sc * 16, _sb + _c * 8, 16); \
        } \
    } \
    CP_COMMIT(); \
} while (0)

    ISSUE(0); ISSUE(1);

    for (int it = 0; it < chunks; it++) {
        CP_WAIT(1);
        __syncthreads();
        ISSUE(it + 2);
        uint32_t sA = smb + (it % NSTAGE) * STG_BYTES;
        uint32_t sB = sA + TILE_BYTES;
#pragma unroll
        for (int ks = 0; ks < 4; ks++) {
            int ca = ks * 2 + acb;
            uint32_t a[2][4];
            ldsm4(a[0], sA + aoff[0] + ((ca ^ arx[0]) << 4));
            ldsm4(a[1], sA + aoff[1] + ((ca ^ arx[1]) << 4));
            int cb = ks * 2 + bcb;
#pragma unroll
            for (int nfp = 0; nfp < 4; nfp++) {
                uint32_t bb[4];
                ldsm4(bb, sB + boff[nfp] + ((cb ^ brx[nfp]) << 4));
                mma_f16(c[0][2 * nfp],     a[0], bb[0], bb[1]);
                mma_f16(c[1][2 * nfp],     a[1], bb[0], bb[1]);
                mma_f16(c[0][2 * nfp + 1], a[0], bb[2], bb[3]);
                mma_f16(c[1][2 * nfp + 1], a[1], bb[2], bb[3]);
            }
        }
        __syncthreads();
    }
    CP_WAIT(0);

    float* Pp = P + (size_t)blockIdx.y * pstride;
#pragma unroll
    for (int mf = 0; mf < 2; mf++) {
        int r0 = m0 + warp_m0 + mf * 16 + g;
#pragma unroll
        for (int nf = 0; nf < 8; nf++) {
            int col = warp_n0 + nf * 8 + t * 2;
            if (r0 < M)
                *(float2*)&Pp[(size_t)r0 * CC + col] = make_float2(c[mf][nf][0], c[mf][nf][1]);
            if (r0 + 8 < M)
                *(float2*)&Pp[(size_t)(r0 + 8) * CC + col] = make_float2(c[mf][nf][2], c[mf][nf][3]);
        }
    }
#undef ISSUE
}

// ---------------- combine split-K partials + BN column sums -------------------
template <int SP>
__global__ void k_comb(const float* __restrict__ P, int pstride, int M,
                       float* __restrict__ out, float* __restrict__ red) {
    int c = threadIdx.x;
    float s = 0.f, s2 = 0.f;
    for (int r = blockIdx.x; r < M; r += gridDim.x) {
        size_t o = (size_t)r * CC + c;
        float v = P[o];
        if (SP > 1) v += P[pstride + o];
        if (SP > 2) v += P[2 * (size_t)pstride + o];
        out[o] = v;
        s += v; s2 += v * v;
    }
    atomicAdd(&red[c], s);
    atomicAdd(&red[CC + c], s2);
}

__global__ void k_stats(const float* __restrict__ red, const float* __restrict__ g,
                        const float* __restrict__ be, float* __restrict__ sc,
                        float* __restrict__ sh, int M) {
    int c = threadIdx.x;
    float mu = red[c] / (float)M;
    float var = red[CC + c] / (float)M - mu * mu;
    float s = g[c] * rsqrtf(var + 1e-5f);
    sc[c] = s;
    sh[c] = be[c] - mu * s;
}

__global__ void k_bnelu(const float* __restrict__ X, const float* __restrict__ sc,
                        const float* __restrict__ sh, __half* __restrict__ Y, int n) {
    int i = blockIdx.x * blockDim.x + threadIdx.x;
    if (i >= n) return;
    int c = i & (CC - 1);
    float v = X[i] * sc[c] + sh[c];
    Y[i] = __float2half(v > 0.f ? v : expm1f(v));
}

__global__ void k_final(const float* __restrict__ A, const float* __restrict__ B,
                        const float* __restrict__ sc2, const float* __restrict__ sh2,
                        const float* __restrict__ scS, const float* __restrict__ shS,
                        float* __restrict__ out, int n) {
    int i = blockIdx.x * blockDim.x + threadIdx.x;
    if (i >= n) return;
    int c = i & (CC - 1);
    float v = A[i] * sc2[c] + sh2[c] + B[i] * scS[c] + shS[c];
    out[i] = v > 0.f ? v : expm1f(v);
}

// ---------------- launch ----------------------------------------------------
extern "C" void kernel_launch(void* const* d_in, const int* in_sizes, int n_in,
                              void* d_out, int out_size) {
    const float* x    = (const float*)d_in[0];
    const int*   ei   = (const int*)d_in[1];
    const float* attr = (const float*)d_in[2];
    const float* W1   = (const float*)d_in[3];
    const float* Wr1  = (const float*)d_in[4];
    const float* g1   = (const float*)d_in[6];
    const float* be1  = (const float*)d_in[7];
    const float* W2   = (const float*)d_in[8];
    const float* Wr2  = (const float*)d_in[9];
    const float* g2   = (const float*)d_in[11];
    const float* be2  = (const float*)d_in[12];
    const float* Wsc  = (const float*)d_in[13];
    const float* Wrsc = (const float*)d_in[14];
    const float* gsc  = (const float*)d_in[16];
    const float* besc = (const float*)d_in[17];

    int E = in_sizes[1] / 2;
    int M = in_sizes[0] / CI1;
    const int* src = ei;
    const int* dst = ei + E;

    __half *acc, *wt1, *wt2, *wts, *sinb, *h1e;
    float *part, *out1, *out2, *outs, *red, *scale, *shift;
    int *degcnt;
    cudaGetSymbolAddress((void**)&acc,    g_acc);
    cudaGetSymbolAddress((void**)&wt1,    g_wt1);
    cudaGetSymbolAddress((void**)&wt2,    g_wt2);
    cudaGetSymbolAddress((void**)&wts,    g_wts);
    cudaGetSymbolAddress((void**)&sinb,   g_sin);
    cudaGetSymbolAddress((void**)&h1e,    g_h1e);
    cudaGetSymbolAddress((void**)&part,   g_part);
    cudaGetSymbolAddress((void**)&out1,   g_out1);
    cudaGetSymbolAddress((void**)&out2,   g_out2);
    cudaGetSymbolAddress((void**)&outs,   g_outs);
    cudaGetSymbolAddress((void**)&red,    g_red);
    cudaGetSymbolAddress((void**)&scale,  g_scale);
    cudaGetSymbolAddress((void**)&shift,  g_shift);
    cudaGetSymbolAddress((void**)&degcnt, g_degcnt);

    int dsm = NSTAGE * STG_BYTES;   // 96KB
    cudaFuncSetAttribute(k_mgemm, cudaFuncAttributeMaxDynamicSharedMemorySize, dsm);
    cudaFuncSetAttribute((const void*)k_agg<CC, 0, __half>,
                         cudaFuncAttributeMaxDynamicSharedMemorySize, KT * CC * 4);

    int eb = (E + 255) / 256;
    int mtiles = (M + 127) / 128;
    int pstride = M * CC;

    cudaMemsetAsync(degcnt, 0, M * sizeof(int));
    cudaMemsetAsync(red, 0, 6 * CC * sizeof(float));

    // CSR build
    k_pre<<<eb, 256>>>(dst, E);
    k_scan<<<1, 1024>>>(M);
    k_fill<<<eb, 256>>>(attr, src, dst, E);

    // conv1 agg (+fused shortcut agg), weight transposes, conv1 GEMM
    k_agg<CI1, 1, float><<<M, 512, KT * CI1 * 4>>>(x, x, LD1);
    k_transp3<<<dim3(LD2 / 32, CC / 32, 3), dim3(32, 8)>>>(
        W1, Wr1, W2, Wr2, Wsc, Wrsc, wt1, wt2, wts);
    k_mgemm<<<dim3(mtiles, 3), 256, dsm>>>(acc, wt1, LD1, M, part, pstride,
                                           (LD1 / BK) / 3);
    k_comb<3><<<256, CC>>>(part, pstride, M, out1, red);
    k_stats<<<1, CC>>>(red, g1, be1, scale, shift, M);
    k_bnelu<<<(M * CC + 255) / 256, 256>>>(out1, scale, shift, h1e, M * CC);

    // conv2: full-width aggregation (512 thr, 64KB smem), GEMM splitK=3
    k_agg<CC, 0, __half><<<M, 512, KT * CC * 4>>>(h1e, x, LD2);
    k_mgemm<<<dim3(mtiles, 3), 256, dsm>>>(acc, wt2, LD2, M, part, pstride,
                                           (LD2 / BK) / 3);
    k_comb<3><<<256, CC>>>(part, pstride, M, out2, red + 2 * CC);
    k_stats<<<1, CC>>>(red + 2 * CC, g2, be2, scale + CC, shift + CC, M);

    // shortcut: [mean_agg | x] @ [Wsc ; Wrsc]
    k_mgemm<<<dim3(mtiles, 1), 256, dsm>>>(sinb, wts, CC, M, part, pstride, CC / BK);
    k_comb<1><<<256, CC>>>(part, pstride, M, outs, red + 4 * CC);
    k_stats<<<1, CC>>>(red + 4 * CC, gsc, besc, scale + 2 * CC, shift + 2 * CC, M);

    // final elu(bn2(h) + bnsc(s))
    k_final<<<(M * CC + 255) / 256, 256>>>(out2, outs, scale + CC, shift + CC,
                                           scale + 2 * CC, shift + 2 * CC,
                                           (float*)d_out, M * CC);
}

// round 14
// speedup vs baseline: 1.0221x; 1.0221x over previous
#include <cuda_runtime.h>
#include <cuda_fp16.h>
#include <math.h>
#include <stdint.h>

#define NMAX 10000
#define EMAX 160000
#define KT   125
#define CI1  64
#define CC   128
#define LD1  (KT*CI1 + CI1)    // 8064
#define LD2  (KT*CC + CC)      // 16128

// ---------------- scratch (device globals: no allocations allowed) ----------
__device__ __align__(1024) __half g_acc[(size_t)NMAX * LD2];  // 322MB
__device__ __align__(1024) __half g_wt1[CC * LD1];
__device__ __align__(1024) __half g_wt2[CC * LD2];
__device__ __align__(1024) __half g_wts[CC * CC];
__device__ __align__(1024) __half g_sin[NMAX * CC];           // [s_agg | x]
__device__ __align__(1024) __half g_h1e[NMAX * CC];           // elu(bn1(conv1)) fp16
__device__ __align__(1024) float g_part[3 * (size_t)NMAX * CC];
__device__ __align__(1024) float g_out1[NMAX * CC];
__device__ __align__(1024) float g_out2[NMAX * CC];
__device__ __align__(1024) float g_outs[NMAX * CC];
__device__ __align__(16) float g_w8  [EMAX * 8];   // CSR-ordered basis weights
__device__ __align__(16) int   g_idx8[EMAX * 8];   // CSR-ordered kernel indices
__device__ int   g_srco[EMAX];
__device__ int   g_rowptr[NMAX + 1];
__device__ int   g_cursor[NMAX];
__device__ int   g_degcnt[NMAX];
__device__ float g_red  [6 * CC];
__device__ float g_scale[3 * CC];
__device__ float g_shift[3 * CC];

// ---------------- helpers ----------------------------------------------------
__device__ __forceinline__ uint32_t smem_u32(const void* p) {
    uint32_t a;
    asm("{ .reg .u64 t; cvta.to.shared.u64 t, %1; cvt.u32.u64 %0, t; }" : "=r"(a) : "l"(p));
    return a;
}
__device__ __forceinline__ void cp_async16(uint32_t dst, const void* src, int vsize) {
    asm volatile("cp.async.cg.shared.global [%0], [%1], 16, %2;"
                 :: "r"(dst), "l"(src), "r"(vsize) : "memory");
}
#define CP_COMMIT() asm volatile("cp.async.commit_group;" ::: "memory")
#define CP_WAIT(n)  asm volatile("cp.async.wait_group %0;" :: "n"(n) : "memory")

__device__ __forceinline__ void ldsm4(uint32_t* r, uint32_t addr) {
    asm volatile("ldmatrix.sync.aligned.m8n8.x4.shared.b16 {%0,%1,%2,%3}, [%4];"
                 : "=r"(r[0]), "=r"(r[1]), "=r"(r[2]), "=r"(r[3]) : "r"(addr));
}
__device__ __forceinline__ void mma_f16(float* c, const uint32_t* a, uint32_t b0, uint32_t b1) {
    asm volatile("mma.sync.aligned.m16n8k16.row.col.f32.f16.f16.f32 "
                 "{%0,%1,%2,%3}, {%4,%5,%6,%7}, {%8,%9}, {%0,%1,%2,%3};"
                 : "+f"(c[0]), "+f"(c[1]), "+f"(c[2]), "+f"(c[3])
                 : "r"(a[0]), "r"(a[1]), "r"(a[2]), "r"(a[3]), "r"(b0), "r"(b1));
}

// ---------------- CSR build --------------------------------------------------
__global__ void k_pre(const int* __restrict__ dst, int E) {
    int e = blockIdx.x * blockDim.x + threadIdx.x;
    if (e < E) atomicAdd(&g_degcnt[dst[e]], 1);
}

__global__ void k_scan(int n) {
    __shared__ int sh[1024];
    __shared__ int carry;
    int t = threadIdx.x;
    if (t == 0) carry = 0;
    __syncthreads();
    for (int base = 0; base < n; base += 1024) {
        int i = base + t;
        int v = (i < n) ? g_degcnt[i] : 0;
        sh[t] = v;
        __syncthreads();
        for (int off = 1; off < 1024; off <<= 1) {
            int tv = (t >= off) ? sh[t - off] : 0;
            __syncthreads();
            sh[t] += tv;
            __syncthreads();
        }
        if (i < n) {
            int ex = carry + sh[t] - v;
            g_rowptr[i] = ex;
            g_cursor[i] = ex;
        }
        __syncthreads();
        if (t == 0) carry += sh[1023];
        __syncthreads();
    }
    if (t == 0) g_rowptr[n] = carry;
}

// CSR fill (also zeros BN reduction buffers; runs before any k_comb)
__global__ void k_fill(const float* __restrict__ attr, const int* __restrict__ src,
                       const int* __restrict__ dst, int E) {
    if (blockIdx.x == 0) {
        for (int i = threadIdx.x; i < 6 * CC; i += blockDim.x) g_red[i] = 0.f;
    }
    int e = blockIdx.x * blockDim.x + threadIdx.x;
    if (e >= E) return;
    int pos = atomicAdd(&g_cursor[dst[e]], 1);
    g_srco[pos] = src[e];
    float v0 = attr[e * 3 + 0] * 4.f, v1 = attr[e * 3 + 1] * 4.f, v2 = attr[e * 3 + 2] * 4.f;
    float b0 = floorf(v0), b1 = floorf(v1), b2 = floorf(v2);
    float f0 = v0 - b0, f1 = v1 - b1, f2 = v2 - b2;
    int i0 = (int)b0, i1 = (int)b1, i2 = (int)b2;
#pragma unroll
    for (int m = 0; m < 8; m++) {
        int t0 = m & 1, t1 = (m >> 1) & 1, t2 = (m >> 2) & 1;
        float w = (t0 ? f0 : 1.f - f0) * (t1 ? f1 : 1.f - f1) * (t2 ? f2 : 1.f - f2);
        int c0 = min(max(i0 + t0, 0), 4);
        int c1 = min(max(i1 + t1, 0), 4);
        int c2 = min(max(i2 + t2, 0), 4);
        g_idx8[pos * 8 + m] = (c0 * 5 + c1) * 5 + c2;
        g_w8[pos * 8 + m] = w;
    }
}

// ---------------- aggregation: NT thr = (NT/CIT) edge-groups x CIT channels --
template <int CIT, int NT, int WITH_S, typename T>
__global__ __launch_bounds__(NT)
void k_agg(const T* __restrict__ X, const float* __restrict__ Xroot, int ldacc) {
    extern __shared__ float acc[];      // KT*CIT floats
    __shared__ float sred[NT];
    const int GR = NT / CIT;
    int n = blockIdx.x;
    int tid = threadIdx.x;
    int c = tid & (CIT - 1), grp = tid / CIT;
    float4 z4 = make_float4(0.f, 0.f, 0.f, 0.f);
    for (int i = tid; i < KT * CIT / 4; i += NT) ((float4*)acc)[i] = z4;
    int jb = g_rowptr[n], je = g_rowptr[n + 1];
    float invd = (je > jb) ? 1.f / (float)(je - jb) : 1.f;
    float ss = 0.f;
    __syncthreads();

    const int4*   ip = (const int4*)g_idx8;
    const float4* wp = (const float4*)g_w8;
    for (int j = jb + grp; j < je; j += GR) {
        float xc = (float)X[(size_t)g_srco[j] * CIT + c];
        int4 ca = ip[j * 2], cb = ip[j * 2 + 1];
        float4 va = wp[j * 2], vb = wp[j * 2 + 1];
        if (WITH_S) ss += xc;
        atomicAdd(&acc[ca.x * CIT + c], va.x * xc);
        atomicAdd(&acc[ca.y * CIT + c], va.y * xc);
        atomicAdd(&acc[ca.z * CIT + c], va.z * xc);
        atomicAdd(&acc[ca.w * CIT + c], va.w * xc);
        atomicAdd(&acc[cb.x * CIT + c], vb.x * xc);
        atomicAdd(&acc[cb.y * CIT + c], vb.y * xc);
        atomicAdd(&acc[cb.z * CIT + c], vb.z * xc);
        atomicAdd(&acc[cb.w * CIT + c], vb.w * xc);
    }
    __syncthreads();

    // vectorized streaming writeout: float4 -> 4 halves (one 8B .cs store)
    size_t base = (size_t)n * ldacc;
    for (int i = tid; i < KT * CIT / 4; i += NT) {
        float4 v = ((const float4*)acc)[i];
        int bin = i / (CIT / 4);
        int ch  = (i % (CIT / 4)) * 4;
        __half2 h0 = __floats2half2_rn(v.x * invd, v.y * invd);
        __half2 h1 = __floats2half2_rn(v.z * invd, v.w * invd);
        float2 pk = make_float2(__uint_as_float(*(uint32_t*)&h0),
                                __uint_as_float(*(uint32_t*)&h1));
        __stcs((float2*)(g_acc + base + (size_t)bin * CIT + ch), pk);
    }
    if (tid < CIT)
        g_acc[base + (size_t)KT * CIT + tid] = (__half)(float)X[(size_t)n * CIT + tid];
    if (WITH_S) {
        sred[tid] = ss;
        __syncthreads();
        if (tid < 64) {
            float s = 0.f;
#pragma unroll
            for (int q = 0; q < GR; q++) s += sred[tid + q * 64];
            g_sin[n * CC + tid]       = __float2half(s * invd);
            g_sin[n * CC + CI1 + tid] = __float2half(Xroot[n * CI1 + tid]);
        }
    }
}

// fused tiled transpose of all three weight sets -> wt[n][k] fp16.
// Block (0,0,0) also zeros g_degcnt (this kernel runs first; stream order
// guarantees completion before k_pre).
__global__ void k_transp3(const float* __restrict__ W1, const float* __restrict__ Wr1,
                          const float* __restrict__ W2, const float* __restrict__ Wr2,
                          const float* __restrict__ Ws, const float* __restrict__ Wrs,
                          __half* __restrict__ wt1, __half* __restrict__ wt2,
                          __half* __restrict__ wts, int M) {
    __shared__ float tile[32][33];
    int tid = threadIdx.y * 32 + threadIdx.x;
    if (blockIdx.x == 0 && blockIdx.y == 0 && blockIdx.z == 0) {
        for (int i = tid; i < M; i += 256) g_degcnt[i] = 0;
    }
    const float *W, *Wr; __half* out; int Kmain, Ktot;
    if (blockIdx.z == 0) { W = W1; Wr = Wr1; out = wt1; Kmain = KT * CI1; Ktot = LD1; }
    else if (blockIdx.z == 1) { W = W2; Wr = Wr2; out = wt2; Kmain = KT * CC; Ktot = LD2; }
    else { W = Ws; Wr = Wrs; out = wts; Kmain = CI1; Ktot = CC; }
    int kb = blockIdx.x * 32, nb = blockIdx.y * 32;
    if (kb >= Ktot) return;
    int tx = threadIdx.x, ty = threadIdx.y;
#pragma unroll
    for (int i = 0; i < 32; i += 8) {
        int k = kb + ty + i;
        const float* srcp = (k < Kmain) ? &W[(size_t)k * CC] : &Wr[(size_t)(k - Kmain) * CC];
        tile[ty + i][tx] = srcp[nb + tx];
    }
    __syncthreads();
#pragma unroll
    for (int i = 0; i < 32; i += 8) {
        int nn = nb + ty + i;
        out[(size_t)nn * Ktot + kb + tx] = __float2half(tile[tx][ty + i]);
    }
}

// ---------------- fp16 mma.sync GEMM with ldmatrix feed -----------------------
#define BK 64
#define NSTAGE 3
#define STG_BYTES 32768
#define TILE_BYTES 16384

__global__ __launch_bounds__(256, 2)
void k_mgemm(const __half* __restrict__ A, const __half* __restrict__ B, int ld,
             int M, float* __restrict__ P, int pstride, int chunks) {
    extern __shared__ char sm[];
    int tid = threadIdx.x, lane = tid & 31, wid = tid >> 5;
    int m0 = blockIdx.x * 128;
    int kb0 = blockIdx.y * chunks * BK;

    int pr_r = tid >> 1;
    int pr_h = (tid & 1) * 4;
    int grow = m0 + pr_r;
    int vA = (grow < M) ? 16 : 0;
    const __half* Abase = A + (size_t)grow * ld + kb0;
    const __half* Bbase = B + (size_t)pr_r * ld + kb0;

    const int warp_m0 = (wid & 3) * 32;
    const int warp_n0 = (wid >> 2) * 64;
    int g = lane >> 2, t = lane & 3;

    uint32_t aoff[2]; int arx[2];
#pragma unroll
    for (int mf = 0; mf < 2; mf++) {
        int r = warp_m0 + mf * 16 + (lane & 15);
        aoff[mf] = r * 128; arx[mf] = r & 7;
    }
    int acb = lane >> 4;
    int grp = lane >> 3;
    int nf_half = grp >> 1, bcb = grp & 1;
    uint32_t boff[4]; int brx[4];
#pragma unroll
    for (int nfp = 0; nfp < 4; nfp++) {
        int r = warp_n0 + (nfp * 2 + nf_half) * 8 + (lane & 7);
        boff[nfp] = r * 128; brx[nfp] = r & 7;
    }

    float c[2][8][4];
#pragma unroll
    for (int i = 0; i < 2; i++)
#pragma unroll
        for (int j = 0; j < 8; j++)
#pragma unroll
            for (int q = 0; q < 4; q++) c[i][j][q] = 0.f;

    uint32_t smb = smem_u32(sm);

#define ISSUE(IT) do { \
    int _it = (IT); \
    if (_it < chunks) { \
        int _s = _it % NSTAGE; \
        uint32_t _dA = smb + _s * STG_BYTES + pr_r * 128; \
        uint32_t _dB = _dA + TILE_BYTES; \
        const __half* _sa = Abase + _it * BK; \
        const __half* _sb = Bbase + _it * BK; \
        _Pragma("unroll") \
        for (int _j = 0; _j < 4; _j++) { \
            int _c = pr_h + _j; \
            int _sc = _c ^ (pr_r & 7); \
            cp_async16(_dA + _sc * 16, _sa + _c * 8, vA); \
            cp_async16(_dB + _sc * 16, _sb + _c * 8, 16); \
        } \
    } \
    CP_COMMIT(); \
} while (0)

    ISSUE(0); ISSUE(1);

    for (int it = 0; it < chunks; it++) {
        CP_WAIT(1);
        __syncthreads();
        ISSUE(it + 2);
        uint32_t sA = smb + (it % NSTAGE) * STG_BYTES;
        uint32_t sB = sA + TILE_BYTES;
#pragma unroll
        for (int ks = 0; ks < 4; ks++) {
            int ca = ks * 2 + acb;
            uint32_t a[2][4];
            ldsm4(a[0], sA + aoff[0] + ((ca ^ arx[0]) << 4));
            ldsm4(a[1], sA + aoff[1] + ((ca ^ arx[1]) << 4));
            int cb = ks * 2 + bcb;
#pragma unroll
            for (int nfp = 0; nfp < 4; nfp++) {
                uint32_t bb[4];
                ldsm4(bb, sB + boff[nfp] + ((cb ^ brx[nfp]) << 4));
                mma_f16(c[0][2 * nfp],     a[0], bb[0], bb[1]);
                mma_f16(c[1][2 * nfp],     a[1], bb[0], bb[1]);
                mma_f16(c[0][2 * nfp + 1], a[0], bb[2], bb[3]);
                mma_f16(c[1][2 * nfp + 1], a[1], bb[2], bb[3]);
            }
        }
        __syncthreads();
    }
    CP_WAIT(0);

    float* Pp = P + (size_t)blockIdx.y * pstride;
#pragma unroll
    for (int mf = 0; mf < 2; mf++) {
        int r0 = m0 + warp_m0 + mf * 16 + g;
#pragma unroll
        for (int nf = 0; nf < 8; nf++) {
            int col = warp_n0 + nf * 8 + t * 2;
            if (r0 < M)
                *(float2*)&Pp[(size_t)r0 * CC + col] = make_float2(c[mf][nf][0], c[mf][nf][1]);
            if (r0 + 8 < M)
                *(float2*)&Pp[(size_t)(r0 + 8) * CC + col] = make_float2(c[mf][nf][2], c[mf][nf][3]);
        }
    }
#undef ISSUE
}

// ---------------- combine split-K partials + BN column sums -------------------
template <int SP>
__global__ void k_comb(const float* __restrict__ P, int pstride, int M,
                       float* __restrict__ out, float* __restrict__ red) {
    int c = threadIdx.x;
    float s = 0.f, s2 = 0.f;
    for (int r = blockIdx.x; r < M; r += gridDim.x) {
        size_t o = (size_t)r * CC + c;
        float v = P[o];
        if (SP > 1) v += P[pstride + o];
        if (SP > 2) v += P[2 * (size_t)pstride + o];
        out[o] = v;
        s += v; s2 += v * v;
    }
    atomicAdd(&red[c], s);
    atomicAdd(&red[CC + c], s2);
}

__global__ void k_stats(const float* __restrict__ red, const float* __restrict__ g,
                        const float* __restrict__ be, float* __restrict__ sc,
                        float* __restrict__ sh, int M) {
    int c = threadIdx.x;
    float mu = red[c] / (float)M;
    float var = red[CC + c] / (float)M - mu * mu;
    float s = g[c] * rsqrtf(var + 1e-5f);
    sc[c] = s;
    sh[c] = be[c] - mu * s;
}

__global__ void k_bnelu(const float* __restrict__ X, const float* __restrict__ sc,
                        const float* __restrict__ sh, __half* __restrict__ Y, int n) {
    int i = blockIdx.x * blockDim.x + threadIdx.x;
    if (i >= n) return;
    int c = i & (CC - 1);
    float v = X[i] * sc[c] + sh[c];
    Y[i] = __float2half(v > 0.f ? v : expm1f(v));
}

__global__ void k_final(const float* __restrict__ A, const float* __restrict__ B,
                        const float* __restrict__ sc2, const float* __restrict__ sh2,
                        const float* __restrict__ scS, const float* __restrict__ shS,
                        float* __restrict__ out, int n) {
    int i = blockIdx.x * blockDim.x + threadIdx.x;
    if (i >= n) return;
    int c = i & (CC - 1);
    float v = A[i] * sc2[c] + sh2[c] + B[i] * scS[c] + shS[c];
    out[i] = v > 0.f ? v : expm1f(v);
}

// ---------------- launch ----------------------------------------------------
extern "C" void kernel_launch(void* const* d_in, const int* in_sizes, int n_in,
                              void* d_out, int out_size) {
    const float* x    = (const float*)d_in[0];
    const int*   ei   = (const int*)d_in[1];
    const float* attr = (const float*)d_in[2];
    const float* W1   = (const float*)d_in[3];
    const float* Wr1  = (const float*)d_in[4];
    const float* g1   = (const float*)d_in[6];
    const float* be1  = (const float*)d_in[7];
    const float* W2   = (const float*)d_in[8];
    const float* Wr2  = (const float*)d_in[9];
    const float* g2   = (const float*)d_in[11];
    const float* be2  = (const float*)d_in[12];
    const float* Wsc  = (const float*)d_in[13];
    const float* Wrsc = (const float*)d_in[14];
    const float* gsc  = (const float*)d_in[16];
    const float* besc = (const float*)d_in[17];

    int E = in_sizes[1] / 2;
    int M = in_sizes[0] / CI1;
    const int* src = ei;
    const int* dst = ei + E;

    __half *acc, *wt1, *wt2, *wts, *sinb, *h1e;
    float *part, *out1, *out2, *outs, *red, *scale, *shift;
    cudaGetSymbolAddress((void**)&acc,    g_acc);
    cudaGetSymbolAddress((void**)&wt1,    g_wt1);
    cudaGetSymbolAddress((void**)&wt2,    g_wt2);
    cudaGetSymbolAddress((void**)&wts,    g_wts);
    cudaGetSymbolAddress((void**)&sinb,   g_sin);
    cudaGetSymbolAddress((void**)&h1e,    g_h1e);
    cudaGetSymbolAddress((void**)&part,   g_part);
    cudaGetSymbolAddress((void**)&out1,   g_out1);
    cudaGetSymbolAddress((void**)&out2,   g_out2);
    cudaGetSymbolAddress((void**)&outs,   g_outs);
    cudaGetSymbolAddress((void**)&red,    g_red);
    cudaGetSymbolAddress((void**)&scale,  g_scale);
    cudaGetSymbolAddress((void**)&shift,  g_shift);

    int dsm = NSTAGE * STG_BYTES;   // 96KB
    cudaFuncSetAttribute(k_mgemm, cudaFuncAttributeMaxDynamicSharedMemorySize, dsm);
    cudaFuncSetAttribute((const void*)k_agg<CC, 512, 0, __half>,
                         cudaFuncAttributeMaxDynamicSharedMemorySize, KT * CC * 4);

    int eb = (E + 255) / 256;
    int mtiles = (M + 127) / 128;
    int pstride = M * CC;

    // launch 0: weight transposes (+ zeros degcnt, stream-ordered before k_pre)
    k_transp3<<<dim3(LD2 / 32, CC / 32, 3), dim3(32, 8)>>>(
        W1, Wr1, W2, Wr2, Wsc, Wrsc, wt1, wt2, wts, M);

    // CSR build: launches 1-3 (k_fill also zeros g_red)
    k_pre<<<eb, 256>>>(dst, E);
    k_scan<<<1, 1024>>>(M);
    k_fill<<<eb, 256>>>(attr, src, dst, E);

    // conv1: agg (launch 4), GEMM (launch 5 — profiled)
    k_agg<CI1, 256, 1, float><<<M, 256, KT * CI1 * 4>>>(x, x, LD1);
    k_mgemm<<<dim3(mtiles, 3), 256, dsm>>>(acc, wt1, LD1, M, part, pstride,
                                           (LD1 / BK) / 3);
    k_comb<3><<<256, CC>>>(part, pstride, M, out1, red);
    k_stats<<<1, CC>>>(red, g1, be1, scale, shift, M);
    k_bnelu<<<(M * CC + 255) / 256, 256>>>(out1, scale, shift, h1e, M * CC);

    // conv2: full-width aggregation (512 thr, 64KB smem), GEMM splitK=3
    k_agg<CC, 512, 0, __half><<<M, 512, KT * CC * 4>>>(h1e, x, LD2);
    k_mgemm<<<dim3(mtiles, 3), 256, dsm>>>(acc, wt2, LD2, M, part, pstride,
                                           (LD2 / BK) / 3);
    k_comb<3><<<256, CC>>>(part, pstride, M, out2, red + 2 * CC);
    k_stats<<<1, CC>>>(red + 2 * CC, g2, be2, scale + CC, shift + CC, M);

    // shortcut: [mean_agg | x] @ [Wsc ; Wrsc]
    k_mgemm<<<dim3(mtiles, 1), 256, dsm>>>(sinb, wts, CC, M, part, pstride, CC / BK);
    k_comb<1><<<256, CC>>>(part, pstride, M, outs, red + 4 * CC);
    k_stats<<<1, CC>>>(red + 4 * CC, gsc, besc, scale + 2 * CC, shift + 2 * CC, M);

    // final elu(bn2(h) + bnsc(s))
    k_final<<<(M * CC + 255) / 256, 256>>>(out2, outs, scale + CC, shift + CC,
                                           scale + 2 * CC, shift + 2 * CC,
                                           (float*)d_out, M * CC);
}

// round 15
// speedup vs baseline: 1.0504x; 1.0277x over previous
#include <cuda_runtime.h>
#include <cuda_fp16.h>
#include <math.h>
#include <stdint.h>

#define NMAX 10000
#define EMAX 160000
#define KT   125
#define CI1  64
#define CC   128
#define LD1  (KT*CI1 + CI1)    // 8064
#define LD2  (KT*CC + CC)      // 16128
#define NTR_BLK 6048           // transpose tiles in k_setup: 504 x 4 x 3

// ---------------- scratch (device globals: no allocations allowed) ----------
__device__ __align__(1024) __half g_acc[(size_t)NMAX * LD2];  // 322MB
__device__ __align__(1024) __half g_wt1[CC * LD1];
__device__ __align__(1024) __half g_wt2[CC * LD2];
__device__ __align__(1024) __half g_wts[CC * CC];
__device__ __align__(1024) __half g_sin[NMAX * CC];           // [s_agg | x]
__device__ __align__(1024) __half g_h1e[NMAX * CC];           // elu(bn1(conv1)) fp16
__device__ __align__(1024) float g_part[4 * (size_t)NMAX * CC];
__device__ __align__(1024) float g_out1[NMAX * CC];
__device__ __align__(1024) float g_out2[NMAX * CC];
__device__ __align__(1024) float g_outs[NMAX * CC];
__device__ __align__(16) float g_w8  [EMAX * 8];   // CSR-ordered basis weights
__device__ __align__(16) int   g_idx8[EMAX * 8];   // CSR-ordered kernel indices
__device__ int   g_srco[EMAX];
__device__ int   g_rowptr[NMAX + 1];
__device__ int   g_cursor[NMAX];
__device__ int   g_degcnt[NMAX];                   // invariant: zero at kernel_launch entry
__device__ float g_red  [6 * CC];
__device__ float g_scale[3 * CC];
__device__ float g_shift[3 * CC];

// ---------------- helpers ----------------------------------------------------
__device__ __forceinline__ uint32_t smem_u32(const void* p) {
    uint32_t a;
    asm("{ .reg .u64 t; cvta.to.shared.u64 t, %1; cvt.u32.u64 %0, t; }" : "=r"(a) : "l"(p));
    return a;
}
__device__ __forceinline__ void cp_async16(uint32_t dst, const void* src, int vsize) {
    asm volatile("cp.async.cg.shared.global [%0], [%1], 16, %2;"
                 :: "r"(dst), "l"(src), "r"(vsize) : "memory");
}
#define CP_COMMIT() asm volatile("cp.async.commit_group;" ::: "memory")
#define CP_WAIT(n)  asm volatile("cp.async.wait_group %0;" :: "n"(n) : "memory")

__device__ __forceinline__ void ldsm4(uint32_t* r, uint32_t addr) {
    asm volatile("ldmatrix.sync.aligned.m8n8.x4.shared.b16 {%0,%1,%2,%3}, [%4];"
                 : "=r"(r[0]), "=r"(r[1]), "=r"(r[2]), "=r"(r[3]) : "r"(addr));
}
__device__ __forceinline__ void mma_f16(float* c, const uint32_t* a, uint32_t b0, uint32_t b1) {
    asm volatile("mma.sync.aligned.m16n8k16.row.col.f32.f16.f16.f32 "
                 "{%0,%1,%2,%3}, {%4,%5,%6,%7}, {%8,%9}, {%0,%1,%2,%3};"
                 : "+f"(c[0]), "+f"(c[1]), "+f"(c[2]), "+f"(c[3])
                 : "r"(a[0]), "r"(a[1]), "r"(a[2]), "r"(a[3]), "r"(b0), "r"(b1));
}

// ---------------- setup: weight transposes UNION degree count ----------------
// blocks [0, NTR_BLK): tiled transpose of {W1|Wr1, W2|Wr2, Wsc|Wrsc} -> fp16 [n][k]
// blocks [NTR_BLK, ...): per-edge atomic degree count (g_degcnt zero on entry)
__global__ __launch_bounds__(256)
void k_setup(const float* __restrict__ W1, const float* __restrict__ Wr1,
             const float* __restrict__ W2, const float* __restrict__ Wr2,
             const float* __restrict__ Ws, const float* __restrict__ Wrs,
             __half* __restrict__ wt1, __half* __restrict__ wt2,
             __half* __restrict__ wts, const int* __restrict__ dst, int E) {
    int b = blockIdx.x;
    if (b >= NTR_BLK) {
        int e = (b - NTR_BLK) * 256 + threadIdx.x;
        if (e < E) atomicAdd(&g_degcnt[dst[e]], 1);
        return;
    }
    __shared__ float tile[32][33];
    int bx = b % 504, by = (b / 504) % 4, bz = b / 2016;
    const float *W, *Wr; __half* out; int Kmain, Ktot;
    if (bz == 0) { W = W1; Wr = Wr1; out = wt1; Kmain = KT * CI1; Ktot = LD1; }
    else if (bz == 1) { W = W2; Wr = Wr2; out = wt2; Kmain = KT * CC; Ktot = LD2; }
    else { W = Ws; Wr = Wrs; out = wts; Kmain = CI1; Ktot = CC; }
    int kb = bx * 32, nb = by * 32;
    if (kb >= Ktot) return;
    int tx = threadIdx.x & 31, ty = threadIdx.x >> 5;
#pragma unroll
    for (int i = 0; i < 32; i += 8) {
        int k = kb + ty + i;
        const float* srcp = (k < Kmain) ? &W[(size_t)k * CC] : &Wr[(size_t)(k - Kmain) * CC];
        tile[ty + i][tx] = srcp[nb + tx];
    }
    __syncthreads();
#pragma unroll
    for (int i = 0; i < 32; i += 8) {
        int nn = nb + ty + i;
        out[(size_t)nn * Ktot + kb + tx] = __float2half(tile[tx][ty + i]);
    }
}

// scan degcnt -> rowptr/cursor; zeroes degcnt on consume (restores invariant)
__global__ void k_scan(int n) {
    __shared__ int sh[1024];
    __shared__ int carry;
    int t = threadIdx.x;
    if (t == 0) carry = 0;
    __syncthreads();
    for (int base = 0; base < n; base += 1024) {
        int i = base + t;
        int v = (i < n) ? g_degcnt[i] : 0;
        if (i < n) g_degcnt[i] = 0;
        sh[t] = v;
        __syncthreads();
        for (int off = 1; off < 1024; off <<= 1) {
            int tv = (t >= off) ? sh[t - off] : 0;
            __syncthreads();
            sh[t] += tv;
            __syncthreads();
        }
        if (i < n) {
            int ex = carry + sh[t] - v;
            g_rowptr[i] = ex;
            g_cursor[i] = ex;
        }
        __syncthreads();
        if (t == 0) carry += sh[1023];
        __syncthreads();
    }
    if (t == 0) g_rowptr[n] = carry;
}

// CSR fill (also zeros BN reduction buffers; runs before any k_comb)
__global__ void k_fill(const float* __restrict__ attr, const int* __restrict__ src,
                       const int* __restrict__ dst, int E) {
    if (blockIdx.x == 0) {
        for (int i = threadIdx.x; i < 6 * CC; i += blockDim.x) g_red[i] = 0.f;
    }
    int e = blockIdx.x * blockDim.x + threadIdx.x;
    if (e >= E) return;
    int pos = atomicAdd(&g_cursor[dst[e]], 1);
    g_srco[pos] = src[e];
    float v0 = attr[e * 3 + 0] * 4.f, v1 = attr[e * 3 + 1] * 4.f, v2 = attr[e * 3 + 2] * 4.f;
    float b0 = floorf(v0), b1 = floorf(v1), b2 = floorf(v2);
    float f0 = v0 - b0, f1 = v1 - b1, f2 = v2 - b2;
    int i0 = (int)b0, i1 = (int)b1, i2 = (int)b2;
#pragma unroll
    for (int m = 0; m < 8; m++) {
        int t0 = m & 1, t1 = (m >> 1) & 1, t2 = (m >> 2) & 1;
        float w = (t0 ? f0 : 1.f - f0) * (t1 ? f1 : 1.f - f1) * (t2 ? f2 : 1.f - f2);
        int c0 = min(max(i0 + t0, 0), 4);
        int c1 = min(max(i1 + t1, 0), 4);
        int c2 = min(max(i2 + t2, 0), 4);
        g_idx8[pos * 8 + m] = (c0 * 5 + c1) * 5 + c2;
        g_w8[pos * 8 + m] = w;
    }
}

// ---------------- aggregation: NT thr = (NT/CIT) edge-groups x CIT channels --
template <int CIT, int NT, int WITH_S, typename T>
__global__ __launch_bounds__(NT)
void k_agg(const T* __restrict__ X, const float* __restrict__ Xroot, int ldacc) {
    extern __shared__ float acc[];
    __shared__ float sred[NT];
    const int GR = NT / CIT;
    int n = blockIdx.x;
    int tid = threadIdx.x;
    int c = tid & (CIT - 1), grp = tid / CIT;
    float4 z4 = make_float4(0.f, 0.f, 0.f, 0.f);
    for (int i = tid; i < KT * CIT / 4; i += NT) ((float4*)acc)[i] = z4;
    int jb = g_rowptr[n], je = g_rowptr[n + 1];
    float invd = (je > jb) ? 1.f / (float)(je - jb) : 1.f;
    float ss = 0.f;
    __syncthreads();

    const int4*   ip = (const int4*)g_idx8;
    const float4* wp = (const float4*)g_w8;
    for (int j = jb + grp; j < je; j += GR) {
        float xc = (float)X[(size_t)g_srco[j] * CIT + c];
        int4 ca = ip[j * 2], cb = ip[j * 2 + 1];
        float4 va = wp[j * 2], vb = wp[j * 2 + 1];
        if (WITH_S) ss += xc;
        atomicAdd(&acc[ca.x * CIT + c], va.x * xc);
        atomicAdd(&acc[ca.y * CIT + c], va.y * xc);
        atomicAdd(&acc[ca.z * CIT + c], va.z * xc);
        atomicAdd(&acc[ca.w * CIT + c], va.w * xc);
        atomicAdd(&acc[cb.x * CIT + c], vb.x * xc);
        atomicAdd(&acc[cb.y * CIT + c], vb.y * xc);
        atomicAdd(&acc[cb.z * CIT + c], vb.z * xc);
        atomicAdd(&acc[cb.w * CIT + c], vb.w * xc);
    }
    __syncthreads();

    size_t base = (size_t)n * ldacc;
    for (int i = tid; i < KT * CIT / 4; i += NT) {
        float4 v = ((const float4*)acc)[i];
        int bin = i / (CIT / 4);
        int ch  = (i % (CIT / 4)) * 4;
        __half2 h0 = __floats2half2_rn(v.x * invd, v.y * invd);
        __half2 h1 = __floats2half2_rn(v.z * invd, v.w * invd);
        float2 pk = make_float2(__uint_as_float(*(uint32_t*)&h0),
                                __uint_as_float(*(uint32_t*)&h1));
        __stcs((float2*)(g_acc + base + (size_t)bin * CIT + ch), pk);
    }
    if (tid < CIT)
        g_acc[base + (size_t)KT * CIT + tid] = (__half)(float)X[(size_t)n * CIT + tid];
    if (WITH_S) {
        sred[tid] = ss;
        __syncthreads();
        if (tid < 64) {
            float s = 0.f;
#pragma unroll
            for (int q = 0; q < GR; q++) s += sred[tid + q * 64];
            g_sin[n * CC + tid]       = __float2half(s * invd);
            g_sin[n * CC + CI1 + tid] = __float2half(Xroot[n * CI1 + tid]);
        }
    }
}

// ---------------- fp16 mma.sync GEMM with ldmatrix feed -----------------------
// blockIdx.y < nsplit: main GEMM split-K slice y. If scFlag and y == nsplit:
// shortcut GEMM (As/Bs, lds, chunkss) into partial slot nsplit.
#define BK 64
#define NSTAGE 3
#define STG_BYTES 32768
#define TILE_BYTES 16384

__global__ __launch_bounds__(256, 2)
void k_mgemm(const __half* __restrict__ A2, const __half* __restrict__ B2,
             int ld2, int chunks2,
             const __half* __restrict__ As, const __half* __restrict__ Bs,
             int lds, int chunkss,
             int M, float* __restrict__ P, int pstride) {
    extern __shared__ char sm[];
    int tid = threadIdx.x, lane = tid & 31, wid = tid >> 5;
    int m0 = blockIdx.x * 128;
    int y = blockIdx.y;

    const __half *A, *B;
    int ld, chunks, kb0;
    if (As != nullptr && y == gridDim.y - 1) {        // shortcut block
        A = As; B = Bs; ld = lds; chunks = chunkss; kb0 = 0;
    } else {
        A = A2; B = B2; ld = ld2; chunks = chunks2; kb0 = y * chunks2 * BK;
    }

    int pr_r = tid >> 1;
    int pr_h = (tid & 1) * 4;
    int grow = m0 + pr_r;
    int vA = (grow < M) ? 16 : 0;
    const __half* Abase = A + (size_t)grow * ld + kb0;
    const __half* Bbase = B + (size_t)pr_r * ld + kb0;

    const int warp_m0 = (wid & 3) * 32;
    const int warp_n0 = (wid >> 2) * 64;
    int g = lane >> 2, t = lane & 3;

    uint32_t aoff[2]; int arx[2];
#pragma unroll
    for (int mf = 0; mf < 2; mf++) {
        int r = warp_m0 + mf * 16 + (lane & 15);
        aoff[mf] = r * 128; arx[mf] = r & 7;
    }
    int acb = lane >> 4;
    int grp = lane >> 3;
    int nf_half = grp >> 1, bcb = grp & 1;
    uint32_t boff[4]; int brx[4];
#pragma unroll
    for (int nfp = 0; nfp < 4; nfp++) {
        int r = warp_n0 + (nfp * 2 + nf_half) * 8 + (lane & 7);
        boff[nfp] = r * 128; brx[nfp] = r & 7;
    }

    float c[2][8][4];
#pragma unroll
    for (int i = 0; i < 2; i++)
#pragma unroll
        for (int j = 0; j < 8; j++)
#pragma unroll
            for (int q = 0; q < 4; q++) c[i][j][q] = 0.f;

    uint32_t smb = smem_u32(sm);

#define ISSUE(IT) do { \
    int _it = (IT); \
    if (_it < chunks) { \
        int _s = _it % NSTAGE; \
        uint32_t _dA = smb + _s * STG_BYTES + pr_r * 128; \
        uint32_t _dB = _dA + TILE_BYTES; \
        const __half* _sa = Abase + _it * BK; \
        const __half* _sb = Bbase + _it * BK; \
        _Pragma("unroll") \
        for (int _j = 0; _j < 4; _j++) { \
            int _c = pr_h + _j; \
            int _sc = _c ^ (pr_r & 7); \
            cp_async16(_dA + _sc * 16, _sa + _c * 8, vA); \
            cp_async16(_dB + _sc * 16, _sb + _c * 8, 16); \
        } \
    } \
    CP_COMMIT(); \
} while (0)

    ISSUE(0); ISSUE(1);

    for (int it = 0; it < chunks; it++) {
        CP_WAIT(1);
        __syncthreads();
        ISSUE(it + 2);
        uint32_t sA = smb + (it % NSTAGE) * STG_BYTES;
        uint32_t sB = sA + TILE_BYTES;
#pragma unroll
        for (int ks = 0; ks < 4; ks++) {
            int ca = ks * 2 + acb;
            uint32_t a[2][4];
            ldsm4(a[0], sA + aoff[0] + ((ca ^ arx[0]) << 4));
            ldsm4(a[1], sA + aoff[1] + ((ca ^ arx[1]) << 4));
            int cb = ks * 2 + bcb;
#pragma unroll
            for (int nfp = 0; nfp < 4; nfp++) {
                uint32_t bb[4];
                ldsm4(bb, sB + boff[nfp] + ((cb ^ brx[nfp]) << 4));
                mma_f16(c[0][2 * nfp],     a[0], bb[0], bb[1]);
                mma_f16(c[1][2 * nfp],     a[1], bb[0], bb[1]);
                mma_f16(c[0][2 * nfp + 1], a[0], bb[2], bb[3]);
                mma_f16(c[1][2 * nfp + 1], a[1], bb[2], bb[3]);
            }
        }
        __syncthreads();
    }
    CP_WAIT(0);

    float* Pp = P + (size_t)y * pstride;
#pragma unroll
    for (int mf = 0; mf < 2; mf++) {
        int r0 = m0 + warp_m0 + mf * 16 + g;
#pragma unroll
        for (int nf = 0; nf < 8; nf++) {
            int col = warp_n0 + nf * 8 + t * 2;
            if (r0 < M)
                *(float2*)&Pp[(size_t)r0 * CC + col] = make_float2(c[mf][nf][0], c[mf][nf][1]);
            if (r0 + 8 < M)
                *(float2*)&Pp[(size_t)(r0 + 8) * CC + col] = make_float2(c[mf][nf][2], c[mf][nf][3]);
        }
    }
#undef ISSUE
}

// ---------------- combine split-K partials + BN column sums -------------------
template <int SP>
__global__ void k_comb(const float* __restrict__ P, int pstride, int M,
                       float* __restrict__ out, float* __restrict__ red) {
    int c = threadIdx.x;
    float s = 0.f, s2 = 0.f;
    for (int r = blockIdx.x; r < M; r += gridDim.x) {
        size_t o = (size_t)r * CC + c;
        float v = P[o];
        if (SP > 1) v += P[pstride + o];
        if (SP > 2) v += P[2 * (size_t)pstride + o];
        out[o] = v;
        s += v; s2 += v * v;
    }
    atomicAdd(&red[c], s);
    atomicAdd(&red[CC + c], s2);
}

// combined conv2 (slots 0-2) + shortcut (slot 3) partial-combine
__global__ void k_comb2S(const float* __restrict__ P, int pstride, int M,
                         float* __restrict__ out2, float* __restrict__ outs,
                         float* __restrict__ red) {
    int c = threadIdx.x;
    const float* Pb = (blockIdx.y == 0) ? P : P + 3 * (size_t)pstride;
    float* out = (blockIdx.y == 0) ? out2 : outs;
    float* rd  = red + (blockIdx.y == 0 ? 2 * CC : 4 * CC);
    float s = 0.f, s2 = 0.f;
    for (int r = blockIdx.x; r < M; r += gridDim.x) {
        size_t o = (size_t)r * CC + c;
        float v = Pb[o];
        if (blockIdx.y == 0) v += Pb[pstride + o] + Pb[2 * (size_t)pstride + o];
        out[o] = v;
        s += v; s2 += v * v;
    }
    atomicAdd(&rd[c], s);
    atomicAdd(&rd[CC + c], s2);
}

__global__ void k_stats(const float* __restrict__ red, const float* __restrict__ g,
                        const float* __restrict__ be, float* __restrict__ sc,
                        float* __restrict__ sh, int M) {
    int c = threadIdx.x;
    float mu = red[c] / (float)M;
    float var = red[CC + c] / (float)M - mu * mu;
    float s = g[c] * rsqrtf(var + 1e-5f);
    sc[c] = s;
    sh[c] = be[c] - mu * s;
}

// combined conv2 + shortcut stats in one 256-thread launch
__global__ void k_stats2S(const float* __restrict__ red,
                          const float* __restrict__ g2, const float* __restrict__ be2,
                          const float* __restrict__ gs, const float* __restrict__ bes,
                          float* __restrict__ sc, float* __restrict__ sh, int M) {
    int tid = threadIdx.x;
    int c = tid & (CC - 1);
    int which = tid >> 7;
    const float* rd = red + (which ? 4 * CC : 2 * CC);
    const float* gg = which ? gs : g2;
    const float* bb = which ? bes : be2;
    float* scp = sc + (which ? 2 * CC : CC);
    float* shp = sh + (which ? 2 * CC : CC);
    float mu = rd[c] / (float)M;
    float var = rd[CC + c] / (float)M - mu * mu;
    float s = gg[c] * rsqrtf(var + 1e-5f);
    scp[c] = s;
    shp[c] = bb[c] - mu * s;
}

__global__ void k_bnelu(const float* __restrict__ X, const float* __restrict__ sc,
                        const float* __restrict__ sh, __half* __restrict__ Y, int n) {
    int i = blockIdx.x * blockDim.x + threadIdx.x;
    if (i >= n) return;
    int c = i & (CC - 1);
    float v = X[i] * sc[c] + sh[c];
    Y[i] = __float2half(v > 0.f ? v : expm1f(v));
}

__global__ void k_final(const float* __restrict__ A, const float* __restrict__ B,
                        const float* __restrict__ sc2, const float* __restrict__ sh2,
                        const float* __restrict__ scS, const float* __restrict__ shS,
                        float* __restrict__ out, int n) {
    int i = blockIdx.x * blockDim.x + threadIdx.x;
    if (i >= n) return;
    int c = i & (CC - 1);
    float v = A[i] * sc2[c] + sh2[c] + B[i] * scS[c] + shS[c];
    out[i] = v > 0.f ? v : expm1f(v);
}

// ---------------- launch ----------------------------------------------------
extern "C" void kernel_launch(void* const* d_in, const int* in_sizes, int n_in,
                              void* d_out, int out_size) {
    const float* x    = (const float*)d_in[0];
    const int*   ei   = (const int*)d_in[1];
    const float* attr = (const float*)d_in[2];
    const float* W1   = (const float*)d_in[3];
    const float* Wr1  = (const float*)d_in[4];
    const float* g1   = (const float*)d_in[6];
    const float* be1  = (const float*)d_in[7];
    const float* W2   = (const float*)d_in[8];
    const float* Wr2  = (const float*)d_in[9];
    const float* g2   = (const float*)d_in[11];
    const float* be2  = (const float*)d_in[12];
    const float* Wsc  = (const float*)d_in[13];
    const float* Wrsc = (const float*)d_in[14];
    const float* gsc  = (const float*)d_in[16];
    const float* besc = (const float*)d_in[17];

    int E = in_sizes[1] / 2;
    int M = in_sizes[0] / CI1;
    const int* src = ei;
    const int* dst = ei + E;

    __half *acc, *wt1, *wt2, *wts, *sinb, *h1e;
    float *part, *out1, *out2, *outs, *red, *scale, *shift;
    cudaGetSymbolAddress((void**)&acc,    g_acc);
    cudaGetSymbolAddress((void**)&wt1,    g_wt1);
    cudaGetSymbolAddress((void**)&wt2,    g_wt2);
    cudaGetSymbolAddress((void**)&wts,    g_wts);
    cudaGetSymbolAddress((void**)&sinb,   g_sin);
    cudaGetSymbolAddress((void**)&h1e,    g_h1e);
    cudaGetSymbolAddress((void**)&part,   g_part);
    cudaGetSymbolAddress((void**)&out1,   g_out1);
    cudaGetSymbolAddress((void**)&out2,   g_out2);
    cudaGetSymbolAddress((void**)&outs,   g_outs);
    cudaGetSymbolAddress((void**)&red,    g_red);
    cudaGetSymbolAddress((void**)&scale,  g_scale);
    cudaGetSymbolAddress((void**)&shift,  g_shift);

    int dsm = NSTAGE * STG_BYTES;   // 96KB
    cudaFuncSetAttribute(k_mgemm, cudaFuncAttributeMaxDynamicSharedMemorySize, dsm);
    cudaFuncSetAttribute((const void*)k_agg<CC, 512, 0, __half>,
                         cudaFuncAttributeMaxDynamicSharedMemorySize, KT * CC * 4);

    int eb = (E + 255) / 256;
    int mtiles = (M + 127) / 128;
    int pstride = M * CC;

    // launch 0: weight transposes ∪ degree count (degcnt zero by invariant)
    k_setup<<<NTR_BLK + eb, 256>>>(W1, Wr1, W2, Wr2, Wsc, Wrsc,
                                   wt1, wt2, wts, dst, E);
    // CSR: scan (zeroes degcnt on consume), fill (zeroes g_red)
    k_scan<<<1, 1024>>>(M);
    k_fill<<<eb, 256>>>(attr, src, dst, E);

    // conv1: agg (+fused shortcut agg), GEMM splitK=3
    k_agg<CI1, 256, 1, float><<<M, 256, KT * CI1 * 4>>>(x, x, LD1);
    k_mgemm<<<dim3(mtiles, 3), 256, dsm>>>(acc, wt1, LD1, (LD1 / BK) / 3,
                                           nullptr, nullptr, 0, 0,
                                           M, part, pstride);
    k_comb<3><<<256, CC>>>(part, pstride, M, out1, red);
    k_stats<<<1, CC>>>(red, g1, be1, scale, shift, M);
    k_bnelu<<<(M * CC + 255) / 256, 256>>>(out1, scale, shift, h1e, M * CC);

    // conv2 agg; then conv2 GEMM (splitK=3) ∪ shortcut GEMM in ONE launch
    k_agg<CC, 512, 0, __half><<<M, 512, KT * CC * 4>>>(h1e, x, LD2);
    k_mgemm<<<dim3(mtiles, 4), 256, dsm>>>(acc, wt2, LD2, (LD2 / BK) / 3,
                                           sinb, wts, CC, CC / BK,
                                           M, part, pstride);
    // combined combines + combined stats
    k_comb2S<<<dim3(256, 2), CC>>>(part, pstride, M, out2, outs, red);
    k_stats2S<<<1, 256>>>(red, g2, be2, gsc, besc, scale, shift, M);

    // final elu(bn2(h) + bnsc(s))
    k_final<<<(M * CC + 255) / 256, 256>>>(out2, outs, scale + CC, shift + CC,
                                           scale + 2 * CC, shift + 2 * CC,
                                           (float*)d_out, M * CC);
}

// round 16
// speedup vs baseline: 1.1163x; 1.0627x over previous
#include <cuda_runtime.h>
#include <cuda.h>
#include <cuda_fp16.h>
#include <math.h>
#include <stdint.h>

#define NMAX 10000
#define EMAX 160000
#define KT   125
#define CI1  64
#define CC   128
#define LD1  (KT*CI1 + CI1)    // 8064
#define LD2  (KT*CC + CC)      // 16128
#define NTR_BLK 6048           // transpose tiles in k_setup: 504 x 4 x 3

// ---------------- scratch (device globals: no allocations allowed) ----------
__device__ __align__(1024) __half g_acc[(size_t)NMAX * LD2];  // 322MB
__device__ __align__(1024) __half g_wt1[CC * LD1];
__device__ __align__(1024) __half g_wt2[CC * LD2];
__device__ __align__(1024) __half g_wts[CC * CC];
__device__ __align__(1024) __half g_sin[NMAX * CC];           // [s_agg | x]
__device__ __align__(1024) __half g_h1e[NMAX * CC];           // elu(bn1(conv1)) fp16
__device__ __align__(1024) float g_part[4 * (size_t)NMAX * CC];
__device__ __align__(1024) float g_out1[NMAX * CC];
__device__ __align__(1024) float g_out2[NMAX * CC];
__device__ __align__(1024) float g_outs[NMAX * CC];
__device__ __align__(16) float g_w8  [EMAX * 8];
__device__ __align__(16) int   g_idx8[EMAX * 8];
__device__ int   g_srco[EMAX];
__device__ int   g_rowptr[NMAX + 1];
__device__ int   g_cursor[NMAX];
__device__ int   g_degcnt[NMAX];                   // invariant: zero at entry
__device__ float g_red  [6 * CC];
__device__ float g_scale[3 * CC];
__device__ float g_shift[3 * CC];

// ---------------- helpers ----------------------------------------------------
__device__ __forceinline__ uint32_t smem_u32(const void* p) {
    uint32_t a;
    asm("{ .reg .u64 t; cvta.to.shared.u64 t, %1; cvt.u32.u64 %0, t; }" : "=r"(a) : "l"(p));
    return a;
}
__device__ __forceinline__ void ldsm4(uint32_t* r, uint32_t addr) {
    asm volatile("ldmatrix.sync.aligned.m8n8.x4.shared.b16 {%0,%1,%2,%3}, [%4];"
                 : "=r"(r[0]), "=r"(r[1]), "=r"(r[2]), "=r"(r[3]) : "r"(addr));
}
__device__ __forceinline__ void mma_f16(float* c, const uint32_t* a, uint32_t b0, uint32_t b1) {
    asm volatile("mma.sync.aligned.m16n8k16.row.col.f32.f16.f16.f32 "
                 "{%0,%1,%2,%3}, {%4,%5,%6,%7}, {%8,%9}, {%0,%1,%2,%3};"
                 : "+f"(c[0]), "+f"(c[1]), "+f"(c[2]), "+f"(c[3])
                 : "r"(a[0]), "r"(a[1]), "r"(a[2]), "r"(a[3]), "r"(b0), "r"(b1));
}
#define MBAR_INIT(a, c) \
    asm volatile("mbarrier.init.shared.b64 [%0], %1;" :: "r"(a), "r"((uint32_t)(c)) : "memory")
#define MBAR_EXPECT_TX(a, b) \
    asm volatile("mbarrier.arrive.expect_tx.shared.b64 _, [%0], %1;" :: "r"(a), "r"((uint32_t)(b)) : "memory")
#define MBAR_ARRIVE(a) \
    asm volatile("mbarrier.arrive.shared.b64 _, [%0];" :: "r"(a) : "memory")
#define MBAR_WAIT(a, ph) do { \
    uint32_t _m = (a), _p = (ph), _d; \
    asm volatile("{\n\t.reg .pred p;\n\tmbarrier.try_wait.parity.acquire.cta.shared::cta.b64 p, [%1], %2;\n\tselp.b32 %0, 1, 0, p;\n\t}" \
        : "=r"(_d) : "r"(_m), "r"(_p) : "memory"); \
    if (!_d) { \
        asm volatile("{\n\t.reg .pred P1;\n\tWL_%=:\n\tmbarrier.try_wait.parity.acquire.cta.shared::cta.b64 P1, [%0], %1, 0x989680;\n\t@P1 bra.uni WD_%=;\n\tbra.uni WL_%=;\n\tWD_%=:\n\t}" \
            :: "r"(_m), "r"(_p) : "memory"); \
    } } while (0)
#define TMA2D(smemaddr, tmap, cx, cy, mbar) \
    asm volatile("cp.async.bulk.tensor.2d.shared::cta.global.tile.mbarrier::complete_tx::bytes " \
                 "[%0], [%1, {%2, %3}], [%4];" \
                 :: "r"(smemaddr), "l"(tmap), "r"(cx), "r"(cy), "r"(mbar) : "memory")

// ---------------- setup: weight transposes UNION degree count ----------------
__global__ __launch_bounds__(256)
void k_setup(const float* __restrict__ W1, const float* __restrict__ Wr1,
             const float* __restrict__ W2, const float* __restrict__ Wr2,
             const float* __restrict__ Ws, const float* __restrict__ Wrs,
             __half* __restrict__ wt1, __half* __restrict__ wt2,
             __half* __restrict__ wts, const int* __restrict__ dst, int E) {
    int b = blockIdx.x;
    if (b >= NTR_BLK) {
        int e = (b - NTR_BLK) * 256 + threadIdx.x;
        if (e < E) atomicAdd(&g_degcnt[dst[e]], 1);
        return;
    }
    __shared__ float tile[32][33];
    int bx = b % 504, by = (b / 504) % 4, bz = b / 2016;
    const float *W, *Wr; __half* out; int Kmain, Ktot;
    if (bz == 0) { W = W1; Wr = Wr1; out = wt1; Kmain = KT * CI1; Ktot = LD1; }
    else if (bz == 1) { W = W2; Wr = Wr2; out = wt2; Kmain = KT * CC; Ktot = LD2; }
    else { W = Ws; Wr = Wrs; out = wts; Kmain = CI1; Ktot = CC; }
    int kb = bx * 32, nb = by * 32;
    if (kb >= Ktot) return;
    int tx = threadIdx.x & 31, ty = threadIdx.x >> 5;
#pragma unroll
    for (int i = 0; i < 32; i += 8) {
        int k = kb + ty + i;
        const float* srcp = (k < Kmain) ? &W[(size_t)k * CC] : &Wr[(size_t)(k - Kmain) * CC];
        tile[ty + i][tx] = srcp[nb + tx];
    }
    __syncthreads();
#pragma unroll
    for (int i = 0; i < 32; i += 8) {
        int nn = nb + ty + i;
        out[(size_t)nn * Ktot + kb + tx] = __float2half(tile[tx][ty + i]);
    }
}

// scan degcnt -> rowptr/cursor; zeroes degcnt on consume
__global__ void k_scan(int n) {
    __shared__ int sh[1024];
    __shared__ int carry;
    int t = threadIdx.x;
    if (t == 0) carry = 0;
    __syncthreads();
    for (int base = 0; base < n; base += 1024) {
        int i = base + t;
        int v = (i < n) ? g_degcnt[i] : 0;
        if (i < n) g_degcnt[i] = 0;
        sh[t] = v;
        __syncthreads();
        for (int off = 1; off < 1024; off <<= 1) {
            int tv = (t >= off) ? sh[t - off] : 0;
            __syncthreads();
            sh[t] += tv;
            __syncthreads();
        }
        if (i < n) {
            int ex = carry + sh[t] - v;
            g_rowptr[i] = ex;
            g_cursor[i] = ex;
        }
        __syncthreads();
        if (t == 0) carry += sh[1023];
        __syncthreads();
    }
    if (t == 0) g_rowptr[n] = carry;
}

__global__ void k_fill(const float* __restrict__ attr, const int* __restrict__ src,
                       const int* __restrict__ dst, int E) {
    if (blockIdx.x == 0) {
        for (int i = threadIdx.x; i < 6 * CC; i += blockDim.x) g_red[i] = 0.f;
    }
    int e = blockIdx.x * blockDim.x + threadIdx.x;
    if (e >= E) return;
    int pos = atomicAdd(&g_cursor[dst[e]], 1);
    g_srco[pos] = src[e];
    float v0 = attr[e * 3 + 0] * 4.f, v1 = attr[e * 3 + 1] * 4.f, v2 = attr[e * 3 + 2] * 4.f;
    float b0 = floorf(v0), b1 = floorf(v1), b2 = floorf(v2);
    float f0 = v0 - b0, f1 = v1 - b1, f2 = v2 - b2;
    int i0 = (int)b0, i1 = (int)b1, i2 = (int)b2;
#pragma unroll
    for (int m = 0; m < 8; m++) {
        int t0 = m & 1, t1 = (m >> 1) & 1, t2 = (m >> 2) & 1;
        float w = (t0 ? f0 : 1.f - f0) * (t1 ? f1 : 1.f - f1) * (t2 ? f2 : 1.f - f2);
        int c0 = min(max(i0 + t0, 0), 4);
        int c1 = min(max(i1 + t1, 0), 4);
        int c2 = min(max(i2 + t2, 0), 4);
        g_idx8[pos * 8 + m] = (c0 * 5 + c1) * 5 + c2;
        g_w8[pos * 8 + m] = w;
    }
}

// ---------------- aggregation ------------------------------------------------
template <int CIT, int NT, int WITH_S, typename T>
__global__ __launch_bounds__(NT)
void k_agg(const T* __restrict__ X, const float* __restrict__ Xroot, int ldacc) {
    extern __shared__ float acc[];
    __shared__ float sred[NT];
    const int GR = NT / CIT;
    int n = blockIdx.x;
    int tid = threadIdx.x;
    int c = tid & (CIT - 1), grp = tid / CIT;
    float4 z4 = make_float4(0.f, 0.f, 0.f, 0.f);
    for (int i = tid; i < KT * CIT / 4; i += NT) ((float4*)acc)[i] = z4;
    int jb = g_rowptr[n], je = g_rowptr[n + 1];
    float invd = (je > jb) ? 1.f / (float)(je - jb) : 1.f;
    float ss = 0.f;
    __syncthreads();

    const int4*   ip = (const int4*)g_idx8;
    const float4* wp = (const float4*)g_w8;
    for (int j = jb + grp; j < je; j += GR) {
        float xc = (float)X[(size_t)g_srco[j] * CIT + c];
        int4 ca = ip[j * 2], cb = ip[j * 2 + 1];
        float4 va = wp[j * 2], vb = wp[j * 2 + 1];
        if (WITH_S) ss += xc;
        atomicAdd(&acc[ca.x * CIT + c], va.x * xc);
        atomicAdd(&acc[ca.y * CIT + c], va.y * xc);
        atomicAdd(&acc[ca.z * CIT + c], va.z * xc);
        atomicAdd(&acc[ca.w * CIT + c], va.w * xc);
        atomicAdd(&acc[cb.x * CIT + c], vb.x * xc);
        atomicAdd(&acc[cb.y * CIT + c], vb.y * xc);
        atomicAdd(&acc[cb.z * CIT + c], vb.z * xc);
        atomicAdd(&acc[cb.w * CIT + c], vb.w * xc);
    }
    __syncthreads();

    size_t base = (size_t)n * ldacc;
    for (int i = tid; i < KT * CIT / 4; i += NT) {
        float4 v = ((const float4*)acc)[i];
        int bin = i / (CIT / 4);
        int ch  = (i % (CIT / 4)) * 4;
        __half2 h0 = __floats2half2_rn(v.x * invd, v.y * invd);
        __half2 h1 = __floats2half2_rn(v.z * invd, v.w * invd);
        float2 pk = make_float2(__uint_as_float(*(uint32_t*)&h0),
                                __uint_as_float(*(uint32_t*)&h1));
        __stcs((float2*)(g_acc + base + (size_t)bin * CIT + ch), pk);
    }
    if (tid < CIT)
        g_acc[base + (size_t)KT * CIT + tid] = (__half)(float)X[(size_t)n * CIT + tid];
    if (WITH_S) {
        sred[tid] = ss;
        __syncthreads();
        if (tid < 64) {
            float s = 0.f;
#pragma unroll
            for (int q = 0; q < GR; q++) s += sred[tid + q * 64];
            g_sin[n * CC + tid]       = __float2half(s * invd);
            g_sin[n * CC + CI1 + tid] = __float2half(Xroot[n * CI1 + tid]);
        }
    }
}

// ---------------- fp16 mma.sync GEMM, TMA-fed (SW128 == our XOR swizzle) ------
#define BK 64
#define NSTAGE 3
#define STG_BYTES 32768
#define TILE_BYTES 16384

__global__ __launch_bounds__(256, 2)
void k_mgemm(const __grid_constant__ CUtensorMap tA2,
             const __grid_constant__ CUtensorMap tB2, int chunks2,
             const __grid_constant__ CUtensorMap tAs,
             const __grid_constant__ CUtensorMap tBs, int chunkss,
             int useS, int M, float* __restrict__ P, int pstride) {
    extern __shared__ char dyn[];
    __shared__ __align__(8) unsigned long long barF[NSTAGE], barD[NSTAGE];
    int tid = threadIdx.x, lane = tid & 31, wid = tid >> 5;
    int m0 = blockIdx.x * 128;
    int y = blockIdx.y;

    const CUtensorMap *tA, *tB;
    int chunks, kx0;
    if (useS && y == gridDim.y - 1) { tA = &tAs; tB = &tBs; chunks = chunkss; kx0 = 0; }
    else { tA = &tA2; tB = &tB2; chunks = chunks2; kx0 = y * chunks2 * BK; }

    uint32_t smb = (smem_u32(dyn) + 1023) & ~1023u;
    if (tid == 0) {
        for (int s = 0; s < NSTAGE; s++) {
            MBAR_INIT(smem_u32(&barF[s]), 1);
            MBAR_INIT(smem_u32(&barD[s]), 256);
        }
    }
    __syncthreads();

    const int warp_m0 = (wid & 3) * 32;
    const int warp_n0 = (wid >> 2) * 64;
    int g = lane >> 2, t = lane & 3;

    uint32_t aoff[2]; int arx[2];
#pragma unroll
    for (int mf = 0; mf < 2; mf++) {
        int r = warp_m0 + mf * 16 + (lane & 15);
        aoff[mf] = r * 128; arx[mf] = r & 7;
    }
    int acb = lane >> 4;
    int grp = lane >> 3;
    int nf_half = grp >> 1, bcb = grp & 1;
    uint32_t boff[4]; int brx[4];
#pragma unroll
    for (int nfp = 0; nfp < 4; nfp++) {
        int r = warp_n0 + (nfp * 2 + nf_half) * 8 + (lane & 7);
        boff[nfp] = r * 128; brx[nfp] = r & 7;
    }

    float c[2][8][4];
#pragma unroll
    for (int i = 0; i < 2; i++)
#pragma unroll
        for (int j = 0; j < 8; j++)
#pragma unroll
            for (int q = 0; q < 4; q++) c[i][j][q] = 0.f;

    for (int it = 0; it < chunks; it++) {
        int s = it % NSTAGE;
        int f = it / NSTAGE;
        if (tid == 0) {                          // producer: 2 TMA issues/iter
            if (it >= NSTAGE) MBAR_WAIT(smem_u32(&barD[s]), (f - 1) & 1);
            MBAR_EXPECT_TX(smem_u32(&barF[s]), STG_BYTES);
            uint32_t dA = smb + s * STG_BYTES;
            TMA2D(dA, tA, kx0 + it * BK, m0, smem_u32(&barF[s]));
            TMA2D(dA + TILE_BYTES, tB, kx0 + it * BK, 0, smem_u32(&barF[s]));
        }
        MBAR_WAIT(smem_u32(&barF[s]), f & 1);
        uint32_t sA = smb + s * STG_BYTES;
        uint32_t sB = sA + TILE_BYTES;
#pragma unroll
        for (int ks = 0; ks < 4; ks++) {
            int ca = ks * 2 + acb;
            uint32_t a[2][4];
            ldsm4(a[0], sA + aoff[0] + ((ca ^ arx[0]) << 4));
            ldsm4(a[1], sA + aoff[1] + ((ca ^ arx[1]) << 4));
            int cb = ks * 2 + bcb;
#pragma unroll
            for (int nfp = 0; nfp < 4; nfp++) {
                uint32_t bb[4];
                ldsm4(bb, sB + boff[nfp] + ((cb ^ brx[nfp]) << 4));
                mma_f16(c[0][2 * nfp],     a[0], bb[0], bb[1]);
                mma_f16(c[1][2 * nfp],     a[1], bb[0], bb[1]);
                mma_f16(c[0][2 * nfp + 1], a[0], bb[2], bb[3]);
                mma_f16(c[1][2 * nfp + 1], a[1], bb[2], bb[3]);
            }
        }
        MBAR_ARRIVE(smem_u32(&barD[s]));
    }

    float* Pp = P + (size_t)y * pstride;
#pragma unroll
    for (int mf = 0; mf < 2; mf++) {
        int r0 = m0 + warp_m0 + mf * 16 + g;
#pragma unroll
        for (int nf = 0; nf < 8; nf++) {
            int col = warp_n0 + nf * 8 + t * 2;
            if (r0 < M)
                *(float2*)&Pp[(size_t)r0 * CC + col] = make_float2(c[mf][nf][0], c[mf][nf][1]);
            if (r0 + 8 < M)
                *(float2*)&Pp[(size_t)(r0 + 8) * CC + col] = make_float2(c[mf][nf][2], c[mf][nf][3]);
        }
    }
}

// ---------------- combine split-K partials + BN column sums -------------------
template <int SP>
__global__ void k_comb(const float* __restrict__ P, int pstride, int M,
                       float* __restrict__ out, float* __restrict__ red) {
    int c = threadIdx.x;
    float s = 0.f, s2 = 0.f;
    for (int r = blockIdx.x; r < M; r += gridDim.x) {
        size_t o = (size_t)r * CC + c;
        float v = P[o];
        if (SP > 1) v += P[pstride + o];
        if (SP > 2) v += P[2 * (size_t)pstride + o];
        out[o] = v;
        s += v; s2 += v * v;
    }
    atomicAdd(&red[c], s);
    atomicAdd(&red[CC + c], s2);
}

__global__ void k_comb2S(const float* __restrict__ P, int pstride, int M,
                         float* __restrict__ out2, float* __restrict__ outs,
                         float* __restrict__ red) {
    int c = threadIdx.x;
    const float* Pb = (blockIdx.y == 0) ? P : P + 3 * (size_t)pstride;
    float* out = (blockIdx.y == 0) ? out2 : outs;
    float* rd  = red + (blockIdx.y == 0 ? 2 * CC : 4 * CC);
    float s = 0.f, s2 = 0.f;
    for (int r = blockIdx.x; r < M; r += gridDim.x) {
        size_t o = (size_t)r * CC + c;
        float v = Pb[o];
        if (blockIdx.y == 0) v += Pb[pstride + o] + Pb[2 * (size_t)pstride + o];
        out[o] = v;
        s += v; s2 += v * v;
    }
    atomicAdd(&rd[c], s);
    atomicAdd(&rd[CC + c], s2);
}

__global__ void k_stats(const float* __restrict__ red, const float* __restrict__ g,
                        const float* __restrict__ be, float* __restrict__ sc,
                        float* __restrict__ sh, int M) {
    int c = threadIdx.x;
    float mu = red[c] / (float)M;
    float var = red[CC + c] / (float)M - mu * mu;
    float s = g[c] * rsqrtf(var + 1e-5f);
    sc[c] = s;
    sh[c] = be[c] - mu * s;
}

__global__ void k_stats2S(const float* __restrict__ red,
                          const float* __restrict__ g2, const float* __restrict__ be2,
                          const float* __restrict__ gs, const float* __restrict__ bes,
                          float* __restrict__ sc, float* __restrict__ sh, int M) {
    int tid = threadIdx.x;
    int c = tid & (CC - 1);
    int which = tid >> 7;
    const float* rd = red + (which ? 4 * CC : 2 * CC);
    const float* gg = which ? gs : g2;
    const float* bb = which ? bes : be2;
    float* scp = sc + (which ? 2 * CC : CC);
    float* shp = sh + (which ? 2 * CC : CC);
    float mu = rd[c] / (float)M;
    float var = rd[CC + c] / (float)M - mu * mu;
    float s = gg[c] * rsqrtf(var + 1e-5f);
    scp[c] = s;
    shp[c] = bb[c] - mu * s;
}

__global__ void k_bnelu(const float* __restrict__ X, const float* __restrict__ sc,
                        const float* __restrict__ sh, __half* __restrict__ Y, int n) {
    int i = blockIdx.x * blockDim.x + threadIdx.x;
    if (i >= n) return;
    int c = i & (CC - 1);
    float v = X[i] * sc[c] + sh[c];
    Y[i] = __float2half(v > 0.f ? v : expm1f(v));
}

__global__ void k_final(const float* __restrict__ A, const float* __restrict__ B,
                        const float* __restrict__ sc2, const float* __restrict__ sh2,
                        const float* __restrict__ scS, const float* __restrict__ shS,
                        float* __restrict__ out, int n) {
    int i = blockIdx.x * blockDim.x + threadIdx.x;
    if (i >= n) return;
    int c = i & (CC - 1);
    float v = A[i] * sc2[c] + sh2[c] + B[i] * scS[c] + shS[c];
    out[i] = v > 0.f ? v : expm1f(v);
}

// ---------------- host side --------------------------------------------------
typedef CUresult (*PFN_tmapenc)(CUtensorMap*, CUtensorMapDataType, cuuint32_t, void*,
                                const cuuint64_t*, const cuuint64_t*, const cuuint32_t*,
                                const cuuint32_t*, CUtensorMapInterleave, CUtensorMapSwizzle,
                                CUtensorMapL2promotion, CUtensorMapFloatOOBfill);

static void make_map(PFN_tmapenc enc, CUtensorMap* tm, void* base,
                     unsigned long long d0, unsigned long long d1) {
    cuuint64_t dims[2] = {d0, d1};
    cuuint64_t strides[1] = {d0 * 2ull};          // fp16
    cuuint32_t box[2] = {64u, 128u};              // 128B x 128 rows
    cuuint32_t est[2] = {1u, 1u};
    enc(tm, CU_TENSOR_MAP_DATA_TYPE_FLOAT16, 2, base, dims, strides, box, est,
        CU_TENSOR_MAP_INTERLEAVE_NONE, CU_TENSOR_MAP_SWIZZLE_128B,
        CU_TENSOR_MAP_L2_PROMOTION_L2_128B, CU_TENSOR_MAP_FLOAT_OOB_FILL_NONE);
}

extern "C" void kernel_launch(void* const* d_in, const int* in_sizes, int n_in,
                              void* d_out, int out_size) {
    const float* x    = (const float*)d_in[0];
    const int*   ei   = (const int*)d_in[1];
    const float* attr = (const float*)d_in[2];
    const float* W1   = (const float*)d_in[3];
    const float* Wr1  = (const float*)d_in[4];
    const float* g1   = (const float*)d_in[6];
    const float* be1  = (const float*)d_in[7];
    const float* W2   = (const float*)d_in[8];
    const float* Wr2  = (const float*)d_in[9];
    const float* g2   = (const float*)d_in[11];
    const float* be2  = (const float*)d_in[12];
    const float* Wsc  = (const float*)d_in[13];
    const float* Wrsc = (const float*)d_in[14];
    const float* gsc  = (const float*)d_in[16];
    const float* besc = (const float*)d_in[17];

    int E = in_sizes[1] / 2;
    int M = in_sizes[0] / CI1;
    const int* src = ei;
    const int* dst = ei + E;

    __half *acc, *wt1, *wt2, *wts, *sinb, *h1e;
    float *part, *out1, *out2, *outs, *red, *scale, *shift;
    cudaGetSymbolAddress((void**)&acc,    g_acc);
    cudaGetSymbolAddress((void**)&wt1,    g_wt1);
    cudaGetSymbolAddress((void**)&wt2,    g_wt2);
    cudaGetSymbolAddress((void**)&wts,    g_wts);
    cudaGetSymbolAddress((void**)&sinb,   g_sin);
    cudaGetSymbolAddress((void**)&h1e,    g_h1e);
    cudaGetSymbolAddress((void**)&part,   g_part);
    cudaGetSymbolAddress((void**)&out1,   g_out1);
    cudaGetSymbolAddress((void**)&out2,   g_out2);
    cudaGetSymbolAddress((void**)&outs,   g_outs);
    cudaGetSymbolAddress((void**)&red,    g_red);
    cudaGetSymbolAddress((void**)&scale,  g_scale);
    cudaGetSymbolAddress((void**)&shift,  g_shift);

    void* fp = nullptr;
    cudaDriverEntryPointQueryResult qr;
    cudaGetDriverEntryPoint("cuTensorMapEncodeTiled", &fp, cudaEnableDefault, &qr);
    PFN_tmapenc enc = (PFN_tmapenc)fp;

    CUtensorMap tA1, tB1, tA2, tB2, tAs, tBs;
    make_map(enc, &tA1, acc,  LD1, (unsigned long long)M);
    make_map(enc, &tB1, wt1,  LD1, CC);
    make_map(enc, &tA2, acc,  LD2, (unsigned long long)M);
    make_map(enc, &tB2, wt2,  LD2, CC);
    make_map(enc, &tAs, sinb, CC,  (unsigned long long)M);
    make_map(enc, &tBs, wts,  CC,  CC);

    int dsm = NSTAGE * STG_BYTES + 1024;   // 97KB (aligned in kernel)
    cudaFuncSetAttribute(k_mgemm, cudaFuncAttributeMaxDynamicSharedMemorySize, dsm);
    cudaFuncSetAttribute((const void*)k_agg<CC, 512, 0, __half>,
                         cudaFuncAttributeMaxDynamicSharedMemorySize, KT * CC * 4);

    int eb = (E + 255) / 256;
    int mtiles = (M + 127) / 128;
    int pstride = M * CC;

    // launch 0: weight transposes ∪ degree count
    k_setup<<<NTR_BLK + eb, 256>>>(W1, Wr1, W2, Wr2, Wsc, Wrsc,
                                   wt1, wt2, wts, dst, E);
    k_scan<<<1, 1024>>>(M);
    k_fill<<<eb, 256>>>(attr, src, dst, E);

    // conv1: agg (+fused shortcut agg), TMA GEMM splitK=3
    k_agg<CI1, 256, 1, float><<<M, 256, KT * CI1 * 4>>>(x, x, LD1);
    k_mgemm<<<dim3(mtiles, 3), 256, dsm>>>(tA1, tB1, (LD1 / BK) / 3,
                                           tA1, tB1, 0, 0, M, part, pstride);
    k_comb<3><<<256, CC>>>(part, pstride, M, out1, red);
    k_stats<<<1, CC>>>(red, g1, be1, scale, shift, M);
    k_bnelu<<<(M * CC + 255) / 256, 256>>>(out1, scale, shift, h1e, M * CC);

    // conv2 agg; conv2 GEMM (splitK=3) ∪ shortcut GEMM in one launch
    k_agg<CC, 512, 0, __half><<<M, 512, KT * CC * 4>>>(h1e, x, LD2);
    k_mgemm<<<dim3(mtiles, 4), 256, dsm>>>(tA2, tB2, (LD2 / BK) / 3,
                                           tAs, tBs, CC / BK, 1, M, part, pstride);
    k_comb2S<<<dim3(256, 2), CC>>>(part, pstride, M, out2, outs, red);
    k_stats2S<<<1, 256>>>(red, g2, be2, gsc, besc, scale, shift, M);

    // final elu(bn2(h) + bnsc(s))
    k_final<<<(M * CC + 255) / 256, 256>>>(out2, outs, scale + CC, shift + CC,
                                           scale + 2 * CC, shift + 2 * CC,
                                           (float*)d_out, M * CC);
}

// round 17
// speedup vs baseline: 1.2663x; 1.1345x over previous
#include <cuda_runtime.h>
#include <cuda.h>
#include <cuda_fp16.h>
#include <math.h>
#include <stdint.h>

#define NMAX 10000
#define EMAX 160000
#define KT   125
#define CI1  64
#define CC   128
#define LD1  (KT*CI1 + CI1)    // 8064
#define LD2  (KT*CC + CC)      // 16128
#define NTR_BLK 6048           // transpose tiles in k_setup: 504 x 4 x 3

// ---------------- scratch (device globals: no allocations allowed) ----------
__device__ __align__(1024) __half g_acc[(size_t)NMAX * LD2];  // 322MB
__device__ __align__(1024) __half g_wt1[CC * LD1];
__device__ __align__(1024) __half g_wt2[CC * LD2];
__device__ __align__(1024) __half g_wts[CC * CC];
__device__ __align__(1024) __half g_sin[NMAX * CC];           // [s_agg | x]
__device__ __align__(1024) __half g_h1e[NMAX * CC];           // elu(bn1(conv1)) fp16
__device__ __align__(1024) float g_part[4 * (size_t)NMAX * CC];
__device__ __align__(1024) float g_out1[NMAX * CC];
__device__ __align__(1024) float g_out2[NMAX * CC];
__device__ __align__(1024) float g_outs[NMAX * CC];
__device__ __align__(16) float g_w8  [EMAX * 8];
__device__ __align__(16) int   g_idx8[EMAX * 8];
__device__ int   g_srco[EMAX];
__device__ int   g_rowptr[NMAX + 1];
__device__ int   g_cursor[NMAX];
__device__ int   g_degcnt[NMAX];                   // invariant: zero at entry
__device__ float g_red  [6 * CC];
__device__ float g_scale[3 * CC];
__device__ float g_shift[3 * CC];

// ---------------- helpers ----------------------------------------------------
__device__ __forceinline__ uint32_t smem_u32(const void* p) {
    uint32_t a;
    asm("{ .reg .u64 t; cvta.to.shared.u64 t, %1; cvt.u32.u64 %0, t; }" : "=r"(a) : "l"(p));
    return a;
}
__device__ __forceinline__ void ldsm4(uint32_t* r, uint32_t addr) {
    asm volatile("ldmatrix.sync.aligned.m8n8.x4.shared.b16 {%0,%1,%2,%3}, [%4];"
                 : "=r"(r[0]), "=r"(r[1]), "=r"(r[2]), "=r"(r[3]) : "r"(addr));
}
__device__ __forceinline__ void mma_f16(float* c, const uint32_t* a, uint32_t b0, uint32_t b1) {
    asm volatile("mma.sync.aligned.m16n8k16.row.col.f32.f16.f16.f32 "
                 "{%0,%1,%2,%3}, {%4,%5,%6,%7}, {%8,%9}, {%0,%1,%2,%3};"
                 : "+f"(c[0]), "+f"(c[1]), "+f"(c[2]), "+f"(c[3])
                 : "r"(a[0]), "r"(a[1]), "r"(a[2]), "r"(a[3]), "r"(b0), "r"(b1));
}
#define MBAR_INIT(a, c) \
    asm volatile("mbarrier.init.shared.b64 [%0], %1;" :: "r"(a), "r"((uint32_t)(c)) : "memory")
#define MBAR_EXPECT_TX(a, b) \
    asm volatile("mbarrier.arrive.expect_tx.shared.b64 _, [%0], %1;" :: "r"(a), "r"((uint32_t)(b)) : "memory")
#define MBAR_ARRIVE(a) \
    asm volatile("mbarrier.arrive.shared.b64 _, [%0];" :: "r"(a) : "memory")
#define MBAR_WAIT(a, ph) do { \
    uint32_t _m = (a), _p = (ph), _d; \
    asm volatile("{\n\t.reg .pred p;\n\tmbarrier.try_wait.parity.acquire.cta.shared::cta.b64 p, [%1], %2;\n\tselp.b32 %0, 1, 0, p;\n\t}" \
        : "=r"(_d) : "r"(_m), "r"(_p) : "memory"); \
    if (!_d) { \
        asm volatile("{\n\t.reg .pred P1;\n\tWL_%=:\n\tmbarrier.try_wait.parity.acquire.cta.shared::cta.b64 P1, [%0], %1, 0x989680;\n\t@P1 bra.uni WD_%=;\n\tbra.uni WL_%=;\n\tWD_%=:\n\t}" \
            :: "r"(_m), "r"(_p) : "memory"); \
    } } while (0)
#define TMA2D(smemaddr, tmap, cx, cy, mbar) \
    asm volatile("cp.async.bulk.tensor.2d.shared::cta.global.tile.mbarrier::complete_tx::bytes " \
                 "[%0], [%1, {%2, %3}], [%4];" \
                 :: "r"(smemaddr), "l"(tmap), "r"(cx), "r"(cy), "r"(mbar) : "memory")

// ---------------- setup: weight transposes UNION degree count ----------------
__global__ __launch_bounds__(256)
void k_setup(const float* __restrict__ W1, const float* __restrict__ Wr1,
             const float* __restrict__ W2, const float* __restrict__ Wr2,
             const float* __restrict__ Ws, const float* __restrict__ Wrs,
             __half* __restrict__ wt1, __half* __restrict__ wt2,
             __half* __restrict__ wts, const int* __restrict__ dst, int E) {
    int b = blockIdx.x;
    if (b >= NTR_BLK) {
        int e = (b - NTR_BLK) * 256 + threadIdx.x;
        if (e < E) atomicAdd(&g_degcnt[dst[e]], 1);
        return;
    }
    __shared__ float tile[32][33];
    int bx = b % 504, by = (b / 504) % 4, bz = b / 2016;
    const float *W, *Wr; __half* out; int Kmain, Ktot;
    if (bz == 0) { W = W1; Wr = Wr1; out = wt1; Kmain = KT * CI1; Ktot = LD1; }
    else if (bz == 1) { W = W2; Wr = Wr2; out = wt2; Kmain = KT * CC; Ktot = LD2; }
    else { W = Ws; Wr = Wrs; out = wts; Kmain = CI1; Ktot = CC; }
    int kb = bx * 32, nb = by * 32;
    if (kb >= Ktot) return;
    int tx = threadIdx.x & 31, ty = threadIdx.x >> 5;
#pragma unroll
    for (int i = 0; i < 32; i += 8) {
        int k = kb + ty + i;
        const float* srcp = (k < Kmain) ? &W[(size_t)k * CC] : &Wr[(size_t)(k - Kmain) * CC];
        tile[ty + i][tx] = srcp[nb + tx];
    }
    __syncthreads();
#pragma unroll
    for (int i = 0; i < 32; i += 8) {
        int nn = nb + ty + i;
        out[(size_t)nn * Ktot + kb + tx] = __float2half(tile[tx][ty + i]);
    }
}

// scan degcnt -> rowptr/cursor; zeroes degcnt on consume
__global__ void k_scan(int n) {
    __shared__ int sh[1024];
    __shared__ int carry;
    int t = threadIdx.x;
    if (t == 0) carry = 0;
    __syncthreads();
    for (int base = 0; base < n; base += 1024) {
        int i = base + t;
        int v = (i < n) ? g_degcnt[i] : 0;
        if (i < n) g_degcnt[i] = 0;
        sh[t] = v;
        __syncthreads();
        for (int off = 1; off < 1024; off <<= 1) {
            int tv = (t >= off) ? sh[t - off] : 0;
            __syncthreads();
            sh[t] += tv;
            __syncthreads();
        }
        if (i < n) {
            int ex = carry + sh[t] - v;
            g_rowptr[i] = ex;
            g_cursor[i] = ex;
        }
        __syncthreads();
        if (t == 0) carry += sh[1023];
        __syncthreads();
    }
    if (t == 0) g_rowptr[n] = carry;
}

__global__ void k_fill(const float* __restrict__ attr, const int* __restrict__ src,
                       const int* __restrict__ dst, int E) {
    if (blockIdx.x == 0) {
        for (int i = threadIdx.x; i < 6 * CC; i += blockDim.x) g_red[i] = 0.f;
    }
    int e = blockIdx.x * blockDim.x + threadIdx.x;
    if (e >= E) return;
    int pos = atomicAdd(&g_cursor[dst[e]], 1);
    g_srco[pos] = src[e];
    float v0 = attr[e * 3 + 0] * 4.f, v1 = attr[e * 3 + 1] * 4.f, v2 = attr[e * 3 + 2] * 4.f;
    float b0 = floorf(v0), b1 = floorf(v1), b2 = floorf(v2);
    float f0 = v0 - b0, f1 = v1 - b1, f2 = v2 - b2;
    int i0 = (int)b0, i1 = (int)b1, i2 = (int)b2;
#pragma unroll
    for (int m = 0; m < 8; m++) {
        int t0 = m & 1, t1 = (m >> 1) & 1, t2 = (m >> 2) & 1;
        float w = (t0 ? f0 : 1.f - f0) * (t1 ? f1 : 1.f - f1) * (t2 ? f2 : 1.f - f2);
        int c0 = min(max(i0 + t0, 0), 4);
        int c1 = min(max(i1 + t1, 0), 4);
        int c2 = min(max(i2 + t2, 0), 4);
        g_idx8[pos * 8 + m] = (c0 * 5 + c1) * 5 + c2;
        g_w8[pos * 8 + m] = w;
    }
}

// ---------------- aggregation ------------------------------------------------
template <int CIT, int NT, int WITH_S, typename T>
__global__ __launch_bounds__(NT)
void k_agg(const T* __restrict__ X, const float* __restrict__ Xroot, int ldacc) {
    extern __shared__ float acc[];
    __shared__ float sred[NT];
    const int GR = NT / CIT;
    int n = blockIdx.x;
    int tid = threadIdx.x;
    int c = tid & (CIT - 1), grp = tid / CIT;
    float4 z4 = make_float4(0.f, 0.f, 0.f, 0.f);
    for (int i = tid; i < KT * CIT / 4; i += NT) ((float4*)acc)[i] = z4;
    int jb = g_rowptr[n], je = g_rowptr[n + 1];
    float invd = (je > jb) ? 1.f / (float)(je - jb) : 1.f;
    float ss = 0.f;
    __syncthreads();

    const int4*   ip = (const int4*)g_idx8;
    const float4* wp = (const float4*)g_w8;
    for (int j = jb + grp; j < je; j += GR) {
        float xc = (float)X[(size_t)g_srco[j] * CIT + c];
        int4 ca = ip[j * 2], cb = ip[j * 2 + 1];
        float4 va = wp[j * 2], vb = wp[j * 2 + 1];
        if (WITH_S) ss += xc;
        atomicAdd(&acc[ca.x * CIT + c], va.x * xc);
        atomicAdd(&acc[ca.y * CIT + c], va.y * xc);
        atomicAdd(&acc[ca.z * CIT + c], va.z * xc);
        atomicAdd(&acc[ca.w * CIT + c], va.w * xc);
        atomicAdd(&acc[cb.x * CIT + c], vb.x * xc);
        atomicAdd(&acc[cb.y * CIT + c], vb.y * xc);
        atomicAdd(&acc[cb.z * CIT + c], vb.z * xc);
        atomicAdd(&acc[cb.w * CIT + c], vb.w * xc);
    }
    __syncthreads();

    size_t base = (size_t)n * ldacc;
    for (int i = tid; i < KT * CIT / 4; i += NT) {
        float4 v = ((const float4*)acc)[i];
        int bin = i / (CIT / 4);
        int ch  = (i % (CIT / 4)) * 4;
        __half2 h0 = __floats2half2_rn(v.x * invd, v.y * invd);
        __half2 h1 = __floats2half2_rn(v.z * invd, v.w * invd);
        float2 pk = make_float2(__uint_as_float(*(uint32_t*)&h0),
                                __uint_as_float(*(uint32_t*)&h1));
        __stcs((float2*)(g_acc + base + (size_t)bin * CIT + ch), pk);
    }
    if (tid < CIT)
        g_acc[base + (size_t)KT * CIT + tid] = (__half)(float)X[(size_t)n * CIT + tid];
    if (WITH_S) {
        sred[tid] = ss;
        __syncthreads();
        if (tid < 64) {
            float s = 0.f;
#pragma unroll
            for (int q = 0; q < GR; q++) s += sred[tid + q * 64];
            g_sin[n * CC + tid]       = __float2half(s * invd);
            g_sin[n * CC + CI1 + tid] = __float2half(Xroot[n * CI1 + tid]);
        }
    }
}

// ---------------- fp16 mma.sync GEMM, TMA-fed, 2-ahead pipelined --------------
#define BK 64
#define NSTAGE 3
#define STG_BYTES 32768
#define TILE_BYTES 16384

__global__ __launch_bounds__(256, 2)
void k_mgemm(const __grid_constant__ CUtensorMap tA2,
             const __grid_constant__ CUtensorMap tB2, int chunks2,
             const __grid_constant__ CUtensorMap tAs,
             const __grid_constant__ CUtensorMap tBs, int chunkss,
             int useS, int M, float* __restrict__ P, int pstride) {
    extern __shared__ char dyn[];
    __shared__ __align__(8) unsigned long long barF[NSTAGE], barD[NSTAGE];
    int tid = threadIdx.x, lane = tid & 31, wid = tid >> 5;
    int m0 = blockIdx.x * 128;
    int y = blockIdx.y;

    const CUtensorMap *tA, *tB;
    int chunks, kx0;
    if (useS && y == gridDim.y - 1) { tA = &tAs; tB = &tBs; chunks = chunkss; kx0 = 0; }
    else { tA = &tA2; tB = &tB2; chunks = chunks2; kx0 = y * chunks2 * BK; }

    uint32_t smb = (smem_u32(dyn) + 1023) & ~1023u;
    if (tid == 0) {
        for (int s = 0; s < NSTAGE; s++) {
            MBAR_INIT(smem_u32(&barF[s]), 1);
            MBAR_INIT(smem_u32(&barD[s]), 256);
        }
    }
    __syncthreads();

    const int warp_m0 = (wid & 3) * 32;
    const int warp_n0 = (wid >> 2) * 64;
    int g = lane >> 2, t = lane & 3;

    uint32_t aoff[2]; int arx[2];
#pragma unroll
    for (int mf = 0; mf < 2; mf++) {
        int r = warp_m0 + mf * 16 + (lane & 15);
        aoff[mf] = r * 128; arx[mf] = r & 7;
    }
    int acb = lane >> 4;
    int grp = lane >> 3;
    int nf_half = grp >> 1, bcb = grp & 1;
    uint32_t boff[4]; int brx[4];
#pragma unroll
    for (int nfp = 0; nfp < 4; nfp++) {
        int r = warp_n0 + (nfp * 2 + nf_half) * 8 + (lane & 7);
        boff[nfp] = r * 128; brx[nfp] = r & 7;
    }

    float c[2][8][4];
#pragma unroll
    for (int i = 0; i < 2; i++)
#pragma unroll
        for (int j = 0; j < 8; j++)
#pragma unroll
            for (int q = 0; q < 4; q++) c[i][j][q] = 0.f;

    // prologue: issue stages 0..NSTAGE-2 ahead
    if (tid == 0) {
        int npre = (chunks < NSTAGE - 1) ? chunks : NSTAGE - 1;
        for (int p = 0; p < npre; p++) {
            uint32_t dA = smb + p * STG_BYTES;
            MBAR_EXPECT_TX(smem_u32(&barF[p]), STG_BYTES);
            TMA2D(dA, tA, kx0 + p * BK, m0, smem_u32(&barF[p]));
            TMA2D(dA + TILE_BYTES, tB, kx0 + p * BK, 0, smem_u32(&barF[p]));
        }
    }

    for (int it = 0; it < chunks; it++) {
        int s = it % NSTAGE;
        int f = it / NSTAGE;
        MBAR_WAIT(smem_u32(&barF[s]), f & 1);
        int ipre = it + NSTAGE - 1;               // issue 2 ahead
        if (tid == 0 && ipre < chunks) {
            int sp = ipre % NSTAGE, fp = ipre / NSTAGE;
            if (fp > 0) MBAR_WAIT(smem_u32(&barD[sp]), (fp - 1) & 1);
            uint32_t dA = smb + sp * STG_BYTES;
            MBAR_EXPECT_TX(smem_u32(&barF[sp]), STG_BYTES);
            TMA2D(dA, tA, kx0 + ipre * BK, m0, smem_u32(&barF[sp]));
            TMA2D(dA + TILE_BYTES, tB, kx0 + ipre * BK, 0, smem_u32(&barF[sp]));
        }
        uint32_t sA = smb + s * STG_BYTES;
        uint32_t sB = sA + TILE_BYTES;
#pragma unroll
        for (int ks = 0; ks < 4; ks++) {
            int ca = ks * 2 + acb;
            uint32_t a[2][4];
            ldsm4(a[0], sA + aoff[0] + ((ca ^ arx[0]) << 4));
            ldsm4(a[1], sA + aoff[1] + ((ca ^ arx[1]) << 4));
            int cb = ks * 2 + bcb;
#pragma unroll
            for (int nfp = 0; nfp < 4; nfp++) {
                uint32_t bb[4];
                ldsm4(bb, sB + boff[nfp] + ((cb ^ brx[nfp]) << 4));
                mma_f16(c[0][2 * nfp],     a[0], bb[0], bb[1]);
                mma_f16(c[1][2 * nfp],     a[1], bb[0], bb[1]);
                mma_f16(c[0][2 * nfp + 1], a[0], bb[2], bb[3]);
                mma_f16(c[1][2 * nfp + 1], a[1], bb[2], bb[3]);
            }
        }
        MBAR_ARRIVE(smem_u32(&barD[s]));
    }

    float* Pp = P + (size_t)y * pstride;
#pragma unroll
    for (int mf = 0; mf < 2; mf++) {
        int r0 = m0 + warp_m0 + mf * 16 + g;
#pragma unroll
        for (int nf = 0; nf < 8; nf++) {
            int col = warp_n0 + nf * 8 + t * 2;
            if (r0 < M)
                *(float2*)&Pp[(size_t)r0 * CC + col] = make_float2(c[mf][nf][0], c[mf][nf][1]);
            if (r0 + 8 < M)
                *(float2*)&Pp[(size_t)(r0 + 8) * CC + col] = make_float2(c[mf][nf][2], c[mf][nf][3]);
        }
    }
}

// ---------------- combine split-K partials + BN column sums -------------------
template <int SP>
__global__ void k_comb(const float* __restrict__ P, int pstride, int M,
                       float* __restrict__ out, float* __restrict__ red) {
    int c = threadIdx.x;
    float s = 0.f, s2 = 0.f;
    for (int r = blockIdx.x; r < M; r += gridDim.x) {
        size_t o = (size_t)r * CC + c;
        float v = P[o];
        if (SP > 1) v += P[pstride + o];
        if (SP > 2) v += P[2 * (size_t)pstride + o];
        out[o] = v;
        s += v; s2 += v * v;
    }
    atomicAdd(&red[c], s);
    atomicAdd(&red[CC + c], s2);
}

__global__ void k_comb2S(const float* __restrict__ P, int pstride, int M,
                         float* __restrict__ out2, float* __restrict__ outs,
                         float* __restrict__ red) {
    int c = threadIdx.x;
    const float* Pb = (blockIdx.y == 0) ? P : P + 3 * (size_t)pstride;
    float* out = (blockIdx.y == 0) ? out2 : outs;
    float* rd  = red + (blockIdx.y == 0 ? 2 * CC : 4 * CC);
    float s = 0.f, s2 = 0.f;
    for (int r = blockIdx.x; r < M; r += gridDim.x) {
        size_t o = (size_t)r * CC + c;
        float v = Pb[o];
        if (blockIdx.y == 0) v += Pb[pstride + o] + Pb[2 * (size_t)pstride + o];
        out[o] = v;
        s += v; s2 += v * v;
    }
    atomicAdd(&rd[c], s);
    atomicAdd(&rd[CC + c], s2);
}

__global__ void k_stats(const float* __restrict__ red, const float* __restrict__ g,
                        const float* __restrict__ be, float* __restrict__ sc,
                        float* __restrict__ sh, int M) {
    int c = threadIdx.x;
    float mu = red[c] / (float)M;
    float var = red[CC + c] / (float)M - mu * mu;
    float s = g[c] * rsqrtf(var + 1e-5f);
    sc[c] = s;
    sh[c] = be[c] - mu * s;
}

__global__ void k_stats2S(const float* __restrict__ red,
                          const float* __restrict__ g2, const float* __restrict__ be2,
                          const float* __restrict__ gs, const float* __restrict__ bes,
                          float* __restrict__ sc, float* __restrict__ sh, int M) {
    int tid = threadIdx.x;
    int c = tid & (CC - 1);
    int which = tid >> 7;
    const float* rd = red + (which ? 4 * CC : 2 * CC);
    const float* gg = which ? gs : g2;
    const float* bb = which ? bes : be2;
    float* scp = sc + (which ? 2 * CC : CC);
    float* shp = sh + (which ? 2 * CC : CC);
    float mu = rd[c] / (float)M;
    float var = rd[CC + c] / (float)M - mu * mu;
    float s = gg[c] * rsqrtf(var + 1e-5f);
    scp[c] = s;
    shp[c] = bb[c] - mu * s;
}

__global__ void k_bnelu(const float* __restrict__ X, const float* __restrict__ sc,
                        const float* __restrict__ sh, __half* __restrict__ Y, int n) {
    int i = blockIdx.x * blockDim.x + threadIdx.x;
    if (i >= n) return;
    int c = i & (CC - 1);
    float v = X[i] * sc[c] + sh[c];
    Y[i] = __float2half(v > 0.f ? v : expm1f(v));
}

__global__ void k_final(const float* __restrict__ A, const float* __restrict__ B,
                        const float* __restrict__ sc2, const float* __restrict__ sh2,
                        const float* __restrict__ scS, const float* __restrict__ shS,
                        float* __restrict__ out, int n) {
    int i = blockIdx.x * blockDim.x + threadIdx.x;
    if (i >= n) return;
    int c = i & (CC - 1);
    float v = A[i] * sc2[c] + sh2[c] + B[i] * scS[c] + shS[c];
    out[i] = v > 0.f ? v : expm1f(v);
}

// ---------------- host side --------------------------------------------------
typedef CUresult (*PFN_tmapenc)(CUtensorMap*, CUtensorMapDataType, cuuint32_t, void*,
                                const cuuint64_t*, const cuuint64_t*, const cuuint32_t*,
                                const cuuint32_t*, CUtensorMapInterleave, CUtensorMapSwizzle,
                                CUtensorMapL2promotion, CUtensorMapFloatOOBfill);

static void make_map(PFN_tmapenc enc, CUtensorMap* tm, void* base,
                     unsigned long long d0, unsigned long long d1) {
    cuuint64_t dims[2] = {d0, d1};
    cuuint64_t strides[1] = {d0 * 2ull};          // fp16
    cuuint32_t box[2] = {64u, 128u};              // 128B x 128 rows
    cuuint32_t est[2] = {1u, 1u};
    enc(tm, CU_TENSOR_MAP_DATA_TYPE_FLOAT16, 2, base, dims, strides, box, est,
        CU_TENSOR_MAP_INTERLEAVE_NONE, CU_TENSOR_MAP_SWIZZLE_128B,
        CU_TENSOR_MAP_L2_PROMOTION_L2_128B, CU_TENSOR_MAP_FLOAT_OOB_FILL_NONE);
}

extern "C" void kernel_launch(void* const* d_in, const int* in_sizes, int n_in,
                              void* d_out, int out_size) {
    const float* x    = (const float*)d_in[0];
    const int*   ei   = (const int*)d_in[1];
    const float* attr = (const float*)d_in[2];
    const float* W1   = (const float*)d_in[3];
    const float* Wr1  = (const float*)d_in[4];
    const float* g1   = (const float*)d_in[6];
    const float* be1  = (const float*)d_in[7];
    const float* W2   = (const float*)d_in[8];
    const float* Wr2  = (const float*)d_in[9];
    const float* g2   = (const float*)d_in[11];
    const float* be2  = (const float*)d_in[12];
    const float* Wsc  = (const float*)d_in[13];
    const float* Wrsc = (const float*)d_in[14];
    const float* gsc  = (const float*)d_in[16];
    const float* besc = (const float*)d_in[17];

    int E = in_sizes[1] / 2;
    int M = in_sizes[0] / CI1;
    const int* src = ei;
    const int* dst = ei + E;

    __half *acc, *wt1, *wt2, *wts, *sinb, *h1e;
    float *part, *out1, *out2, *outs, *red, *scale, *shift;
    cudaGetSymbolAddress((void**)&acc,    g_acc);
    cudaGetSymbolAddress((void**)&wt1,    g_wt1);
    cudaGetSymbolAddress((void**)&wt2,    g_wt2);
    cudaGetSymbolAddress((void**)&wts,    g_wts);
    cudaGetSymbolAddress((void**)&sinb,   g_sin);
    cudaGetSymbolAddress((void**)&h1e,    g_h1e);
    cudaGetSymbolAddress((void**)&part,   g_part);
    cudaGetSymbolAddress((void**)&out1,   g_out1);
    cudaGetSymbolAddress((void**)&out2,   g_out2);
    cudaGetSymbolAddress((void**)&outs,   g_outs);
    cudaGetSymbolAddress((void**)&red,    g_red);
    cudaGetSymbolAddress((void**)&scale,  g_scale);
    cudaGetSymbolAddress((void**)&shift,  g_shift);

    void* fp = nullptr;
    cudaDriverEntryPointQueryResult qr;
    cudaGetDriverEntryPoint("cuTensorMapEncodeTiled", &fp, cudaEnableDefault, &qr);
    PFN_tmapenc enc = (PFN_tmapenc)fp;

    CUtensorMap tA1, tB1, tA2, tB2, tAs, tBs;
    make_map(enc, &tA1, acc,  LD1, (unsigned long long)M);
    make_map(enc, &tB1, wt1,  LD1, CC);
    make_map(enc, &tA2, acc,  LD2, (unsigned long long)M);
    make_map(enc, &tB2, wt2,  LD2, CC);
    make_map(enc, &tAs, sinb, CC,  (unsigned long long)M);
    make_map(enc, &tBs, wts,  CC,  CC);

    int dsm = NSTAGE * STG_BYTES + 1024;
    cudaFuncSetAttribute(k_mgemm, cudaFuncAttributeMaxDynamicSharedMemorySize, dsm);
    cudaFuncSetAttribute((const void*)k_agg<CC, 512, 0, __half>,
                         cudaFuncAttributeMaxDynamicSharedMemorySize, KT * CC * 4);

    int eb = (E + 255) / 256;
    int mtiles = (M + 127) / 128;
    int pstride = M * CC;

    // launch 0: weight transposes ∪ degree count
    k_setup<<<NTR_BLK + eb, 256>>>(W1, Wr1, W2, Wr2, Wsc, Wrsc,
                                   wt1, wt2, wts, dst, E);
    k_scan<<<1, 1024>>>(M);
    k_fill<<<eb, 256>>>(attr, src, dst, E);

    // conv1: agg (+fused shortcut agg), TMA GEMM splitK=3
    k_agg<CI1, 256, 1, float><<<M, 256, KT * CI1 * 4>>>(x, x, LD1);
    k_mgemm<<<dim3(mtiles, 3), 256, dsm>>>(tA1, tB1, (LD1 / BK) / 3,
                                           tA1, tB1, 0, 0, M, part, pstride);
    k_comb<3><<<256, CC>>>(part, pstride, M, out1, red);
    k_stats<<<1, CC>>>(red, g1, be1, scale, shift, M);
    k_bnelu<<<(M * CC + 255) / 256, 256>>>(out1, scale, shift, h1e, M * CC);

    // conv2 agg; conv2 GEMM (splitK=3) ∪ shortcut GEMM in one launch
    k_agg<CC, 512, 0, __half><<<M, 512, KT * CC * 4>>>(h1e, x, LD2);
    k_mgemm<<<dim3(mtiles, 4), 256, dsm>>>(tA2, tB2, (LD2 / BK) / 3,
                                           tAs, tBs, CC / BK, 1, M, part, pstride);
    k_comb2S<<<dim3(256, 2), CC>>>(part, pstride, M, out2, outs, red);
    k_stats2S<<<1, 256>>>(red, g2, be2, gsc, besc, scale, shift, M);

    // final elu(bn2(h) + bnsc(s))
    k_final<<<(M * CC + 255) / 256, 256>>>(out2, outs, scale + CC, shift + CC,
                                           scale + 2 * CC, shift + 2 * CC,
                                           (float*)d_out, M * CC);
}